// round 10
// baseline (speedup 1.0000x reference)
#include <cuda_runtime.h>
#include <math.h>
#include <stdint.h>

// Problem constants
#define CC    256
#define NTOK  98          // tokens per window (2*7*7)
#define NHD   8
#define NPT   4
#define HDIM  32
#define NWIN  512
#define TOT   (NWIN*NTOK) // 50176 tokens
#define HHH   56
#define WWIDE 56

// ---------------- scratch (static device globals; no allocation) ----------------
__device__ float g_bufA[(size_t)TOT*CC];   // xw  (post-LN1, window order)
__device__ float g_bufB[(size_t)TOT*CC];   // q   / later LN2 output
__device__ float g_bufC[(size_t)TOT*CC];   // value
__device__ float g_bufD[(size_t)TOT*CC];   // attn vector (pre out_w)
__device__ float g_bufE[(size_t)TOT*CC];   // attn out / post-LN
__device__ float g_offb[(size_t)TOT*96];   // offsets
__device__ float g_awb [(size_t)TOT*32];   // attention weights (logits -> softmax)
__device__ float g_hb  [(size_t)TOT*1024]; // fc1 hidden

// ---------------- helpers ----------------
__device__ __forceinline__ float block_reduce_256(float v, float* sh)
{
    #pragma unroll
    for (int o = 16; o > 0; o >>= 1) v += __shfl_down_sync(0xffffffffu, v, o);
    int lane = threadIdx.x & 31, wid = threadIdx.x >> 5;
    if (lane == 0) sh[wid] = v;
    __syncthreads();
    if (wid == 0) {
        v = (lane < 8) ? sh[lane] : 0.f;
        #pragma unroll
        for (int o = 4; o > 0; o >>= 1) v += __shfl_down_sync(0xffffffffu, v, o);
        if (lane == 0) sh[0] = v;
    }
    __syncthreads();
    float r = sh[0];
    __syncthreads();
    return r;
}

__device__ __forceinline__ float gelu_f(float x)
{
    float x3 = x * x * x;
    return 0.5f * x * (1.f + tanhf(0.7978845608028654f * (x + 0.044715f * x3)));
}

// ---------------- stage 1: LN1 + window partition + positional diag -> xw, q ----
__global__ void k_ln1diag(const float* __restrict__ x, const float* __restrict__ mask,
                          const float* __restrict__ g1, const float* __restrict__ b1)
{
    __shared__ float sh[8];
    __shared__ float sdiag;
    int t = blockIdx.x;
    int win = t / NTOK, n = t % NTOK;
    int dwn = win >> 6, hwn = (win >> 3) & 7, wwn = win & 7;
    int wd = n / 49, rm = n % 49, wh = rm / 7, wx = rm % 7;
    int d = dwn * 2 + wd, h = hwn * 7 + wh, w = wwn * 7 + wx;
    size_t g = ((size_t)d * HHH + h) * WWIDE + w;
    int c = threadIdx.x;

    float v = x[g * CC + c];
    float mean = block_reduce_256(v, sh) * (1.f / 256.f);
    float dv = v - mean;
    float var = block_reduce_256(dv * dv, sh) * (1.f / 256.f);
    float xn = dv * rsqrtf(var + 1e-5f) * g1[c] + b1[c];

    if (c == 0) {
        const float* mrow = mask + ((size_t)win * NTOK + n) * NTOK; // z*49+y*7+x layout
        float m = mrow[(wd * 7 + wh) * 7 + wx];
        float zs = 0.f, ys = 0.f, xs = 0.f;
        for (int z = 0; z <= wd; z++) zs += mrow[z * 49 + wh * 7 + wx];
        for (int y = 0; y <= wh; y++) ys += mrow[wd * 49 + y * 7 + wx];
        for (int xq = 0; xq <= wx; xq++) xs += mrow[wd * 49 + wh * 7 + xq];
        const float INV_PI = 0.3183098861837907f;
        const float PI_F   = 3.14159265358979323846f;
        float x_e = xs * m * INV_PI;
        float y_e = ys * m * INV_PI;
        float z_e = zs * m * INV_PI;
        sdiag = m * (sinf(x_e) + sinf(PI_F * y_e) + z_e);
    }
    __syncthreads();
    float diag = sdiag;
    g_bufA[(size_t)t * CC + c] = xn;
    g_bufB[(size_t)t * CC + c] = xn + diag;
}

// ---------------- generic tiled SGEMM: out = A[M,K] @ W[K,N] + bias -------------
// mode 0: plain store  (out[r*N+col])
// mode 1: gelu store
// mode 2: window-reverse + residual:  out[g*256+col] = aux[g*256+col] + v  (N==256)
// mode 3: residual add: out[r*N+col] = aux[r*N+col] + v
__global__ void k_gemm(const float* __restrict__ A, const float* __restrict__ W,
                       const float* __restrict__ bias, float* __restrict__ out,
                       int K, int N, int mode, const float* __restrict__ aux)
{
    __shared__ float As[16][64];
    __shared__ float Bs[16][64];
    int n0   = blockIdx.x * 64;
    int row0 = blockIdx.y * 64;
    int tid = threadIdx.x;
    int tx = tid & 15, ty = tid >> 4;

    int lr = tid >> 2;          // A loader: row 0..63
    int lk = (tid & 3) * 4;     // A loader: k sub-offset
    int bk = tid >> 4;          // B loader: k row 0..15
    int bc = (tid & 15) * 4;    // B loader: col 0..60

    float acc[4][4];
    #pragma unroll
    for (int i = 0; i < 4; i++)
        #pragma unroll
        for (int j = 0; j < 4; j++) acc[i][j] = 0.f;

    for (int k0 = 0; k0 < K; k0 += 16) {
        float4 a4 = *(const float4*)(A + (size_t)(row0 + lr) * K + k0 + lk);
        As[lk + 0][lr] = a4.x; As[lk + 1][lr] = a4.y;
        As[lk + 2][lr] = a4.z; As[lk + 3][lr] = a4.w;

        float4 b4;
        if (n0 + bc < N) b4 = *(const float4*)(W + (size_t)(k0 + bk) * N + n0 + bc);
        else             b4 = make_float4(0.f, 0.f, 0.f, 0.f);
        *(float4*)&Bs[bk][bc] = b4;
        __syncthreads();

        #pragma unroll
        for (int kk = 0; kk < 16; kk++) {
            float4 a = *(const float4*)&As[kk][ty * 4];
            float4 b = *(const float4*)&Bs[kk][tx * 4];
            acc[0][0] += a.x * b.x; acc[0][1] += a.x * b.y; acc[0][2] += a.x * b.z; acc[0][3] += a.x * b.w;
            acc[1][0] += a.y * b.x; acc[1][1] += a.y * b.y; acc[1][2] += a.y * b.z; acc[1][3] += a.y * b.w;
            acc[2][0] += a.z * b.x; acc[2][1] += a.z * b.y; acc[2][2] += a.z * b.z; acc[2][3] += a.z * b.w;
            acc[3][0] += a.w * b.x; acc[3][1] += a.w * b.y; acc[3][2] += a.w * b.z; acc[3][3] += a.w * b.w;
        }
        __syncthreads();
    }

    #pragma unroll
    for (int i = 0; i < 4; i++) {
        int r = row0 + ty * 4 + i;
        size_t gidx = 0;
        if (mode == 2) {
            int win = r / NTOK, n = r % NTOK;
            int dwn = win >> 6, hwn = (win >> 3) & 7, wwn = win & 7;
            int wd = n / 49, rm = n % 49, wh = rm / 7, wx = rm % 7;
            gidx = ((size_t)(dwn * 2 + wd) * HHH + (hwn * 7 + wh)) * WWIDE + (wwn * 7 + wx);
        }
        #pragma unroll
        for (int j = 0; j < 4; j++) {
            int col = n0 + tx * 4 + j;
            if (col < N) {
                float v = acc[i][j] + bias[col];
                if (mode == 0)      out[(size_t)r * N + col] = v;
                else if (mode == 1) out[(size_t)r * N + col] = gelu_f(v);
                else if (mode == 2) out[gidx * 256 + col] = aux[gidx * 256 + col] + v;
                else                out[(size_t)r * N + col] = aux[(size_t)r * N + col] + v;
            }
        }
    }
}

// ---------------- softmax over NP=4 -------------------------------------------
__global__ void k_softmax4(float* __restrict__ a)
{
    int i = blockIdx.x * blockDim.x + threadIdx.x;
    if (i >= TOT * NHD) return;
    float* p = a + (size_t)i * 4;
    float l0 = p[0], l1 = p[1], l2 = p[2], l3 = p[3];
    float m = fmaxf(fmaxf(l0, l1), fmaxf(l2, l3));
    float e0 = __expf(l0 - m), e1 = __expf(l1 - m), e2 = __expf(l2 - m), e3 = __expf(l3 - m);
    float inv = 1.f / (e0 + e1 + e2 + e3);
    p[0] = e0 * inv; p[1] = e1 * inv; p[2] = e2 * inv; p[3] = e3 * inv;
}

// ---------------- deformable trilinear sampling per (window, head) --------------
__global__ void k_sample()
{
    __shared__ float sval[NTOK * HDIM];   // 12.25 KB
    int win  = blockIdx.x >> 3;
    int head = blockIdx.x & 7;

    for (int i = threadIdx.x; i < NTOK * HDIM; i += 256) {
        int s = i >> 5, dch = i & 31;
        sval[i] = g_bufC[((size_t)win * NTOK + s) * CC + head * HDIM + dch];
    }
    __syncthreads();

    int warp = threadIdx.x >> 5, lane = threadIdx.x & 31;
    for (int nn = warp; nn < NTOK; nn += 8) {
        int t = win * NTOK + nn;
        int z = nn / 49, rm = nn % 49, y = rm / 7, xq = rm % 7;
        float rx = (xq + 0.5f) / 7.0f;
        float ry = (y  + 0.5f) / 7.0f;
        float rz = (z  + 0.5f) / 2.0f;
        const float* offp = g_offb + (size_t)t * 96 + head * 12;
        const float* awp  = g_awb  + (size_t)t * 32 + head * 4;
        float tot = 0.f;
        #pragma unroll
        for (int p = 0; p < 4; p++) {
            float ox = offp[p * 3 + 0], oy = offp[p * 3 + 1], oz = offp[p * 3 + 2];
            float aw = awp[p];
            float px = (rx + ox * (1.f / 7.f)) * 7.f - 0.5f;
            float py = (ry + oy * (1.f / 7.f)) * 7.f - 0.5f;
            float pz = (rz + oz * (1.f / 2.f)) * 2.f - 0.5f;
            float x0 = floorf(px), y0 = floorf(py), z0 = floorf(pz);
            float samp = 0.f;
            #pragma unroll
            for (int dz = 0; dz < 2; dz++)
            #pragma unroll
            for (int dy = 0; dy < 2; dy++)
            #pragma unroll
            for (int dx = 0; dx < 2; dx++) {
                float xi = x0 + dx, yi = y0 + dy, zi = z0 + dz;
                float wgt = (1.f - fabsf(px - xi)) * (1.f - fabsf(py - yi)) * (1.f - fabsf(pz - zi));
                bool valid = (xi >= 0.f) && (xi < 7.f) && (yi >= 0.f) && (yi < 7.f) &&
                             (zi >= 0.f) && (zi < 2.f);
                if (valid) {
                    int idx = (((int)zi) * 7 + (int)yi) * 7 + (int)xi;
                    samp += wgt * sval[idx * HDIM + lane];
                }
            }
            tot += aw * samp;
        }
        g_bufD[(size_t)t * CC + head * HDIM + lane] = tot;
    }
}

// ---------------- residual + LN (anorm), window order ---------------------------
__global__ void k_addln(const float* __restrict__ gg, const float* __restrict__ bb)
{
    __shared__ float sh[8];
    int t = blockIdx.x, c = threadIdx.x;
    float v = g_bufA[(size_t)t * CC + c] + g_bufE[(size_t)t * CC + c];
    float mean = block_reduce_256(v, sh) * (1.f / 256.f);
    float dv = v - mean;
    float var = block_reduce_256(dv * dv, sh) * (1.f / 256.f);
    g_bufE[(size_t)t * CC + c] = dv * rsqrtf(var + 1e-5f) * gg[c] + bb[c];
}

// ---------------- LN2 over the (B,D,H,W,C) residual stream ---------------------
__global__ void k_ln2(const float* __restrict__ xin,
                      const float* __restrict__ gg, const float* __restrict__ bb)
{
    __shared__ float sh[8];
    int t = blockIdx.x, c = threadIdx.x;
    float v = xin[(size_t)t * CC + c];
    float mean = block_reduce_256(v, sh) * (1.f / 256.f);
    float dv = v - mean;
    float var = block_reduce_256(dv * dv, sh) * (1.f / 256.f);
    g_bufB[(size_t)t * CC + c] = dv * rsqrtf(var + 1e-5f) * gg[c] + bb[c];
}

// ---------------- launch --------------------------------------------------------
extern "C" void kernel_launch(void* const* d_in, const int* in_sizes, int n_in,
                              void* d_out, int out_size)
{
    (void)in_sizes; (void)n_in; (void)out_size;
    const float* x     = (const float*)d_in[0];
    const float* mask  = (const float*)d_in[1];
    const float* n1g   = (const float*)d_in[2];
    const float* n1b   = (const float*)d_in[3];
    const float* valw  = (const float*)d_in[4];
    const float* valb  = (const float*)d_in[5];
    const float* offw  = (const float*)d_in[6];
    const float* offbi = (const float*)d_in[7];
    const float* aww   = (const float*)d_in[8];
    const float* awbi  = (const float*)d_in[9];
    const float* outw  = (const float*)d_in[10];
    const float* outbi = (const float*)d_in[11];
    const float* ang   = (const float*)d_in[12];
    const float* anb   = (const float*)d_in[13];
    const float* projw = (const float*)d_in[14];
    const float* projb = (const float*)d_in[15];
    const float* n2g   = (const float*)d_in[16];
    const float* n2b   = (const float*)d_in[17];
    const float* fc1w  = (const float*)d_in[18];
    const float* fc1b  = (const float*)d_in[19];
    const float* fc2w  = (const float*)d_in[20];
    const float* fc2b  = (const float*)d_in[21];
    float* out = (float*)d_out;

    float *pA, *pB, *pC, *pD, *pE, *pOff, *pAw, *pH;
    cudaGetSymbolAddress((void**)&pA, g_bufA);
    cudaGetSymbolAddress((void**)&pB, g_bufB);
    cudaGetSymbolAddress((void**)&pC, g_bufC);
    cudaGetSymbolAddress((void**)&pD, g_bufD);
    cudaGetSymbolAddress((void**)&pE, g_bufE);
    cudaGetSymbolAddress((void**)&pOff, g_offb);
    cudaGetSymbolAddress((void**)&pAw,  g_awb);
    cudaGetSymbolAddress((void**)&pH,   g_hb);

    const int MT = TOT / 64;  // 784 row tiles

    // 1. LN1 + partition + diag -> xw (A), q (B)
    k_ln1diag<<<TOT, 256>>>(x, mask, n1g, n1b);
    // 2. value = xw @ val_w + b
    k_gemm<<<dim3(4, MT), 256>>>(pA, valw, valb, pC, 256, 256, 0, nullptr);
    // 3. off = q @ off_w + b ; aw logits = q @ aw_w + b
    k_gemm<<<dim3(2, MT), 256>>>(pB, offw, offbi, pOff, 256, 96, 0, nullptr);
    k_gemm<<<dim3(1, MT), 256>>>(pB, aww, awbi, pAw, 256, 32, 0, nullptr);
    // 4. softmax over NP
    k_softmax4<<<(TOT * NHD + 255) / 256, 256>>>(pAw);
    // 5. deformable trilinear sampling -> attn vector (D)
    k_sample<<<NWIN * NHD, 256>>>();
    // 6. attn out = D @ out_w + b -> E
    k_gemm<<<dim3(4, MT), 256>>>(pD, outw, outbi, pE, 256, 256, 0, nullptr);
    // 7. E = LN(xw + E) with anorm
    k_addln<<<TOT, 256>>>(ang, anb);
    // 8. window-reverse + residual: out = x + (E @ proj_w + b)
    k_gemm<<<dim3(4, MT), 256>>>(pE, projw, projb, out, 256, 256, 2, x);
    // 9. B = LN2(out)
    k_ln2<<<TOT, 256>>>(out, n2g, n2b);
    // 10. H = gelu(B @ fc1_w + b)
    k_gemm<<<dim3(16, MT), 256>>>(pB, fc1w, fc1b, pH, 256, 1024, 1, nullptr);
    // 11. out += H @ fc2_w + b
    k_gemm<<<dim3(4, MT), 256>>>(pH, fc2w, fc2b, out, 1024, 256, 3, out);
}

// round 12
// speedup vs baseline: 1.8775x; 1.8775x over previous
#include <cuda_runtime.h>
#include <cuda_bf16.h>
#include <math.h>
#include <stdint.h>

// Problem constants
#define CC    256
#define NTOK  98
#define NHD   8
#define HDIM  32
#define NWIN  512
#define TOT   (NWIN*NTOK)   // 50176
#define HHH   56
#define WWIDE 56

// ---------------- scratch (static device globals; no allocation) ----------------
__device__ __align__(16) float g_bufA[(size_t)TOT*CC];    // xw fp32 (addln)
__device__ __align__(16) float g_bufC[(size_t)TOT*CC];    // value fp32 (sampler)
__device__ __align__(16) float g_bufE[(size_t)TOT*CC];    // attn-out fp32 (addln)
__device__ __align__(16) float g_offb[(size_t)TOT*96];
__device__ __align__(16) float g_awb [(size_t)TOT*32];
__device__ __align__(16) __nv_bfloat16 g_acth [(size_t)TOT*CC];   // reused act hi
__device__ __align__(16) __nv_bfloat16 g_actl [(size_t)TOT*CC];   // reused act lo
__device__ __align__(16) __nv_bfloat16 g_act2h[(size_t)TOT*CC];   // q hi
__device__ __align__(16) __nv_bfloat16 g_act2l[(size_t)TOT*CC];   // q lo
__device__ __align__(16) __nv_bfloat16 g_hh[(size_t)TOT*1024];    // gelu hidden hi
__device__ __align__(16) __nv_bfloat16 g_hl[(size_t)TOT*1024];    // gelu hidden lo
__device__ __align__(16) __nv_bfloat16 g_wh[262144];              // weights [N,K] hi
__device__ __align__(16) __nv_bfloat16 g_wl[262144];              // weights [N,K] lo

// ---------------- PTX helpers (all base-target features, no 'a' suffix) ---------
__device__ __forceinline__ uint32_t smem_u32(const void* p) {
    uint32_t a;
    asm("{ .reg .u64 t; cvta.to.shared.u64 t, %1; cvt.u32.u64 %0, t; }" : "=r"(a) : "l"(p));
    return a;
}
#define CPASYNC(sa, ga) asm volatile("cp.async.cg.shared.global [%0], [%1], 16;" :: "r"(sa), "l"(ga))
#define CPCOMMIT()      asm volatile("cp.async.commit_group;" ::: "memory")
#define CPWAIT1()       asm volatile("cp.async.wait_group 1;" ::: "memory")
#define CPWAIT0()       asm volatile("cp.async.wait_group 0;" ::: "memory")

__device__ __forceinline__ void ldsm_x4(uint32_t* r, uint32_t a) {
    asm volatile("ldmatrix.sync.aligned.m8n8.x4.shared.b16 {%0,%1,%2,%3}, [%4];"
                 : "=r"(r[0]), "=r"(r[1]), "=r"(r[2]), "=r"(r[3]) : "r"(a));
}
__device__ __forceinline__ void ldsm_x2(uint32_t* r, uint32_t a) {
    asm volatile("ldmatrix.sync.aligned.m8n8.x2.shared.b16 {%0,%1}, [%2];"
                 : "=r"(r[0]), "=r"(r[1]) : "r"(a));
}
__device__ __forceinline__ void mma16816(float* d, const uint32_t* a, const uint32_t* b) {
    asm volatile("mma.sync.aligned.m16n8k16.row.col.f32.bf16.bf16.f32 "
                 "{%0,%1,%2,%3}, {%4,%5,%6,%7}, {%8,%9}, {%0,%1,%2,%3};"
                 : "+f"(d[0]), "+f"(d[1]), "+f"(d[2]), "+f"(d[3])
                 : "r"(a[0]), "r"(a[1]), "r"(a[2]), "r"(a[3]), "r"(b[0]), "r"(b[1]));
}

// ---------------- small helpers ----------------
__device__ __forceinline__ float block_reduce_256(float v, float* sh) {
    #pragma unroll
    for (int o = 16; o > 0; o >>= 1) v += __shfl_down_sync(0xffffffffu, v, o);
    int lane = threadIdx.x & 31, wid = threadIdx.x >> 5;
    if (lane == 0) sh[wid] = v;
    __syncthreads();
    if (wid == 0) {
        v = (lane < 8) ? sh[lane] : 0.f;
        #pragma unroll
        for (int o = 4; o > 0; o >>= 1) v += __shfl_down_sync(0xffffffffu, v, o);
        if (lane == 0) sh[0] = v;
    }
    __syncthreads();
    float r = sh[0];
    __syncthreads();
    return r;
}

__device__ __forceinline__ float gelu_f(float x) {
    float x3 = x * x * x;
    return 0.5f * x * (1.f + tanhf(0.7978845608028654f * (x + 0.044715f * x3)));
}

__device__ __forceinline__ void bsplit(float v, __nv_bfloat16* ph, __nv_bfloat16* pl) {
    __nv_bfloat16 h = __float2bfloat16(v);
    *ph = h;
    *pl = __float2bfloat16(v - __bfloat162float(h));
}

// ---------------- stage 1: LN1 + window partition + positional diag ----
__global__ void k_ln1diag(const float* __restrict__ x, const float* __restrict__ mask,
                          const float* __restrict__ g1, const float* __restrict__ b1)
{
    __shared__ float sh[8];
    __shared__ float sdiag;
    int t = blockIdx.x;
    int win = t / NTOK, n = t % NTOK;
    int dwn = win >> 6, hwn = (win >> 3) & 7, wwn = win & 7;
    int wd = n / 49, rm = n % 49, wh = rm / 7, wx = rm % 7;
    int d = dwn * 2 + wd, h = hwn * 7 + wh, w = wwn * 7 + wx;
    size_t g = ((size_t)d * HHH + h) * WWIDE + w;
    int c = threadIdx.x;

    float v = x[g * CC + c];
    float mean = block_reduce_256(v, sh) * (1.f / 256.f);
    float dv = v - mean;
    float var = block_reduce_256(dv * dv, sh) * (1.f / 256.f);
    float xn = dv * rsqrtf(var + 1e-5f) * g1[c] + b1[c];

    if (c == 0) {
        const float* mrow = mask + ((size_t)win * NTOK + n) * NTOK;
        float m = mrow[(wd * 7 + wh) * 7 + wx];
        float zs = 0.f, ys = 0.f, xs = 0.f;
        for (int z = 0; z <= wd; z++) zs += mrow[z * 49 + wh * 7 + wx];
        for (int y = 0; y <= wh; y++) ys += mrow[wd * 49 + y * 7 + wx];
        for (int xq = 0; xq <= wx; xq++) xs += mrow[wd * 49 + wh * 7 + xq];
        const float INV_PI = 0.3183098861837907f;
        const float PI_F   = 3.14159265358979323846f;
        sdiag = m * (sinf(xs * m * INV_PI) + sinf(PI_F * ys * m * INV_PI) + zs * m * INV_PI);
    }
    __syncthreads();
    float diag = sdiag;
    size_t o = (size_t)t * CC + c;
    g_bufA[o] = xn;
    bsplit(xn, &g_acth[o], &g_actl[o]);
    bsplit(xn + diag, &g_act2h[o], &g_act2l[o]);
}

// ---------------- weight convert (+transpose to [N,K], bf16 hi/lo) ----
__global__ void k_wconv(const float* __restrict__ W, int Kd, int Nd, int rowoff)
{
    int i = blockIdx.x * blockDim.x + threadIdx.x;
    if (i >= Kd * Nd) return;
    int k = i / Nd, n = i % Nd;
    float v = W[(size_t)k * Nd + n];
    size_t o = (size_t)(rowoff + n) * Kd + k;
    bsplit(v, &g_wh[o], &g_wl[o]);
}

// ---------------- split-bf16 mma.sync GEMM -------------------------------------
// C[128,128-tile] = (Ah+Al)[128,K] @ (Bh+Bl)^T[128,K]  via Ah*Bh + Ah*Bl + Al*Bh
// modes: 0 plain fp32 +bias; 2 winrev+residual; 3 residual add;
//        4 gelu -> bf16 hi/lo pair; 5 off/aw column split (N=128, n0=0)
__global__ void __launch_bounds__(256, 1)
k_mgemm(const __nv_bfloat16* __restrict__ Ah, const __nv_bfloat16* __restrict__ Al,
        const __nv_bfloat16* __restrict__ Bh, const __nv_bfloat16* __restrict__ Bl,
        const float* __restrict__ bias, const float* __restrict__ bias2,
        float* __restrict__ out, float* __restrict__ out2,
        const float* __restrict__ aux,
        __nv_bfloat16* __restrict__ outh, __nv_bfloat16* __restrict__ outl,
        int K, int ldo, int mode)
{
    extern __shared__ char smem[];
    constexpr int STG = 65536;   // per-stage: Ah 16K | Al 16K | Bh 16K | Bl 16K
    int tid = threadIdx.x, wid = tid >> 5, lid = tid & 31;
    int row0 = blockIdx.y * 128;
    int n0 = blockIdx.x * 128;
    int nk = K >> 6;

    auto load_stage = [&](int ci, int s) {
        size_t ak = (size_t)row0 * K + ci * 64;
        size_t bk = (size_t)n0 * K + ci * 64;
        char* base = smem + s * STG;
        #pragma unroll
        for (int j = 0; j < 16; j++) {
            int idx = tid + j * 256;
            int seg = idx >> 10;            // 0:Ah 1:Al 2:Bh 3:Bl
            int r = (idx >> 3) & 127;
            int c = idx & 7;
            uint32_t so = (uint32_t)(r * 128 + c * 16);
            so ^= (so >> 3) & 0x70;          // SW128 swizzle
            const __nv_bfloat16* gp;
            if (seg == 0)      gp = Ah + ak + (size_t)r * K + c * 8;
            else if (seg == 1) gp = Al + ak + (size_t)r * K + c * 8;
            else if (seg == 2) gp = Bh + bk + (size_t)r * K + c * 8;
            else               gp = Bl + bk + (size_t)r * K + c * 8;
            CPASYNC(smem_u32(base + seg * 16384 + so), gp);
        }
        CPCOMMIT();
    };

    float acc[4][4][4];
    #pragma unroll
    for (int a = 0; a < 4; a++)
        #pragma unroll
        for (int b = 0; b < 4; b++)
            #pragma unroll
            for (int c = 0; c < 4; c++) acc[a][b][c] = 0.f;

    int warp_m = wid >> 2, warp_n = wid & 3;     // 2 x 4 warp grid, warp tile 64x32
    int lrow_a = lid & 15, lcol_a = (lid >> 4) * 16;
    int l15 = lid & 15;
    int lrow_b = l15 & 7, lcol_b = (l15 >> 3) * 16;

    load_stage(0, 0);
    for (int i = 0; i < nk; i++) {
        if (i + 1 < nk) { load_stage(i + 1, (i + 1) & 1); CPWAIT1(); }
        else            { CPWAIT0(); }
        __syncthreads();
        char* sb = smem + (i & 1) * STG;
        uint32_t aH = smem_u32(sb), aL = aH + 16384, bH = aH + 32768, bL = aH + 49152;
        #pragma unroll
        for (int ks = 0; ks < 4; ks++) {
            int kb = ks * 32;                    // byte offset of 16-elem k group
            uint32_t afh[4][4], afl[4][4], bfh[4][2], bfl[4][2];
            #pragma unroll
            for (int mt = 0; mt < 4; mt++) {
                uint32_t o = (uint32_t)((warp_m * 64 + mt * 16 + lrow_a) * 128 + kb + lcol_a);
                o ^= (o >> 3) & 0x70;
                ldsm_x4(afh[mt], aH + o);
                ldsm_x4(afl[mt], aL + o);
            }
            #pragma unroll
            for (int nt = 0; nt < 4; nt++) {
                uint32_t o = (uint32_t)((warp_n * 32 + nt * 8 + lrow_b) * 128 + kb + lcol_b);
                o ^= (o >> 3) & 0x70;
                ldsm_x2(bfh[nt], bH + o);
                ldsm_x2(bfl[nt], bL + o);
            }
            #pragma unroll
            for (int mt = 0; mt < 4; mt++)
                #pragma unroll
                for (int nt = 0; nt < 4; nt++) {
                    mma16816(acc[mt][nt], afh[mt], bfh[nt]);
                    mma16816(acc[mt][nt], afh[mt], bfl[nt]);
                    mma16816(acc[mt][nt], afl[mt], bfh[nt]);
                }
        }
        __syncthreads();
    }

    // ---- epilogue ----
    int lr = lid >> 2, lc = (lid & 3) * 2;
    #pragma unroll
    for (int mt = 0; mt < 4; mt++) {
        int rbase = row0 + warp_m * 64 + mt * 16 + lr;
        #pragma unroll
        for (int half = 0; half < 2; half++) {
            int r = rbase + half * 8;
            size_t g2 = 0;
            if (mode == 2) {
                int win = r / NTOK, n_ = r % NTOK;
                int dwn = win >> 6, hwn = (win >> 3) & 7, wwn = win & 7;
                int wd = n_ / 49, rm = n_ % 49, wh = rm / 7, wx = rm % 7;
                g2 = ((size_t)(dwn * 2 + wd) * HHH + (hwn * 7 + wh)) * WWIDE + (wwn * 7 + wx);
            }
            #pragma unroll
            for (int nt = 0; nt < 4; nt++) {
                int col = n0 + warp_n * 32 + nt * 8 + lc;
                float v0 = acc[mt][nt][half * 2 + 0];
                float v1 = acc[mt][nt][half * 2 + 1];
                if (mode == 5) {
                    if (col < 96) {
                        v0 += __ldg(bias + col);  v1 += __ldg(bias + col + 1);
                        float2 vv = make_float2(v0, v1);
                        *(float2*)(out + (size_t)r * 96 + col) = vv;
                    } else {
                        v0 += __ldg(bias2 + col - 96);  v1 += __ldg(bias2 + col - 95);
                        float2 vv = make_float2(v0, v1);
                        *(float2*)(out2 + (size_t)r * 32 + (col - 96)) = vv;
                    }
                } else if (mode == 4) {
                    float h0 = gelu_f(v0 + __ldg(bias + col));
                    float h1 = gelu_f(v1 + __ldg(bias + col + 1));
                    __nv_bfloat16 b0 = __float2bfloat16(h0);
                    __nv_bfloat16 b1 = __float2bfloat16(h1);
                    __nv_bfloat162 hi; hi.x = b0; hi.y = b1;
                    __nv_bfloat162 lo;
                    lo.x = __float2bfloat16(h0 - __bfloat162float(b0));
                    lo.y = __float2bfloat16(h1 - __bfloat162float(b1));
                    size_t o = (size_t)r * ldo + col;
                    *(__nv_bfloat162*)(outh + o) = hi;
                    *(__nv_bfloat162*)(outl + o) = lo;
                } else {
                    v0 += __ldg(bias + col);  v1 += __ldg(bias + col + 1);
                    if (mode == 0) {
                        *(float2*)(out + (size_t)r * ldo + col) = make_float2(v0, v1);
                    } else if (mode == 3) {
                        float2 a = *(const float2*)(aux + (size_t)r * ldo + col);
                        *(float2*)(out + (size_t)r * ldo + col) = make_float2(v0 + a.x, v1 + a.y);
                    } else { // mode 2
                        float2 a = *(const float2*)(aux + g2 * 256 + col);
                        *(float2*)(out + g2 * 256 + col) = make_float2(v0 + a.x, v1 + a.y);
                    }
                }
            }
        }
    }
}

// ---------------- softmax over NP=4 -------------------------------------------
__global__ void k_softmax4(float* __restrict__ a)
{
    int i = blockIdx.x * blockDim.x + threadIdx.x;
    if (i >= TOT * NHD) return;
    float* p = a + (size_t)i * 4;
    float l0 = p[0], l1 = p[1], l2 = p[2], l3 = p[3];
    float m = fmaxf(fmaxf(l0, l1), fmaxf(l2, l3));
    float e0 = __expf(l0 - m), e1 = __expf(l1 - m), e2 = __expf(l2 - m), e3 = __expf(l3 - m);
    float inv = 1.f / (e0 + e1 + e2 + e3);
    p[0] = e0 * inv; p[1] = e1 * inv; p[2] = e2 * inv; p[3] = e3 * inv;
}

// ---------------- deformable trilinear sampling -> act bf16 pair ----------------
__global__ void k_sample()
{
    __shared__ float sval[NTOK * HDIM];
    int win  = blockIdx.x >> 3;
    int head = blockIdx.x & 7;

    for (int i = threadIdx.x; i < NTOK * HDIM; i += 256) {
        int s = i >> 5, dch = i & 31;
        sval[i] = g_bufC[((size_t)win * NTOK + s) * CC + head * HDIM + dch];
    }
    __syncthreads();

    int warp = threadIdx.x >> 5, lane = threadIdx.x & 31;
    for (int nn = warp; nn < NTOK; nn += 8) {
        int t = win * NTOK + nn;
        int z = nn / 49, rm = nn % 49, y = rm / 7, xq = rm % 7;
        float rx = (xq + 0.5f) / 7.0f;
        float ry = (y  + 0.5f) / 7.0f;
        float rz = (z  + 0.5f) / 2.0f;
        const float* offp = g_offb + (size_t)t * 96 + head * 12;
        const float* awp  = g_awb  + (size_t)t * 32 + head * 4;
        float tot = 0.f;
        #pragma unroll
        for (int p = 0; p < 4; p++) {
            float ox = offp[p * 3 + 0], oy = offp[p * 3 + 1], oz = offp[p * 3 + 2];
            float aw = awp[p];
            float px = (rx + ox * (1.f / 7.f)) * 7.f - 0.5f;
            float py = (ry + oy * (1.f / 7.f)) * 7.f - 0.5f;
            float pz = (rz + oz * (1.f / 2.f)) * 2.f - 0.5f;
            float x0 = floorf(px), y0 = floorf(py), z0 = floorf(pz);
            float samp = 0.f;
            #pragma unroll
            for (int dz = 0; dz < 2; dz++)
            #pragma unroll
            for (int dy = 0; dy < 2; dy++)
            #pragma unroll
            for (int dx = 0; dx < 2; dx++) {
                float xi = x0 + dx, yi = y0 + dy, zi = z0 + dz;
                float wgt = (1.f - fabsf(px - xi)) * (1.f - fabsf(py - yi)) * (1.f - fabsf(pz - zi));
                bool valid = (xi >= 0.f) && (xi < 7.f) && (yi >= 0.f) && (yi < 7.f) &&
                             (zi >= 0.f) && (zi < 2.f);
                if (valid) {
                    int idx = (((int)zi) * 7 + (int)yi) * 7 + (int)xi;
                    samp += wgt * sval[idx * HDIM + lane];
                }
            }
            tot += aw * samp;
        }
        size_t o = (size_t)t * CC + head * HDIM + lane;
        bsplit(tot, &g_acth[o], &g_actl[o]);
    }
}

// ---------------- residual + LN (anorm) -> act bf16 pair ------------------------
__global__ void k_addln(const float* __restrict__ gg, const float* __restrict__ bb)
{
    __shared__ float sh[8];
    int t = blockIdx.x, c = threadIdx.x;
    size_t o = (size_t)t * CC + c;
    float v = g_bufA[o] + g_bufE[o];
    float mean = block_reduce_256(v, sh) * (1.f / 256.f);
    float dv = v - mean;
    float var = block_reduce_256(dv * dv, sh) * (1.f / 256.f);
    float y = dv * rsqrtf(var + 1e-5f) * gg[c] + bb[c];
    bsplit(y, &g_acth[o], &g_actl[o]);
}

// ---------------- LN2 over residual stream -> act bf16 pair ---------------------
__global__ void k_ln2(const float* __restrict__ xin,
                      const float* __restrict__ gg, const float* __restrict__ bb)
{
    __shared__ float sh[8];
    int t = blockIdx.x, c = threadIdx.x;
    size_t o = (size_t)t * CC + c;
    float v = xin[o];
    float mean = block_reduce_256(v, sh) * (1.f / 256.f);
    float dv = v - mean;
    float var = block_reduce_256(dv * dv, sh) * (1.f / 256.f);
    float y = dv * rsqrtf(var + 1e-5f) * gg[c] + bb[c];
    bsplit(y, &g_acth[o], &g_actl[o]);
}

// ---------------- launch --------------------------------------------------------
extern "C" void kernel_launch(void* const* d_in, const int* in_sizes, int n_in,
                              void* d_out, int out_size)
{
    (void)in_sizes; (void)n_in; (void)out_size;
    const float* x     = (const float*)d_in[0];
    const float* mask  = (const float*)d_in[1];
    const float* n1g   = (const float*)d_in[2];
    const float* n1b   = (const float*)d_in[3];
    const float* valw  = (const float*)d_in[4];
    const float* valb  = (const float*)d_in[5];
    const float* offw  = (const float*)d_in[6];
    const float* offbi = (const float*)d_in[7];
    const float* aww   = (const float*)d_in[8];
    const float* awbi  = (const float*)d_in[9];
    const float* outw  = (const float*)d_in[10];
    const float* outbi = (const float*)d_in[11];
    const float* ang   = (const float*)d_in[12];
    const float* anb   = (const float*)d_in[13];
    const float* projw = (const float*)d_in[14];
    const float* projb = (const float*)d_in[15];
    const float* n2g   = (const float*)d_in[16];
    const float* n2b   = (const float*)d_in[17];
    const float* fc1w  = (const float*)d_in[18];
    const float* fc1b  = (const float*)d_in[19];
    const float* fc2w  = (const float*)d_in[20];
    const float* fc2b  = (const float*)d_in[21];
    float* out = (float*)d_out;

    float *pC, *pE, *pOff, *pAw;
    __nv_bfloat16 *pActh, *pActl, *pAct2h, *pAct2l, *pHh, *pHl, *pWh, *pWl;
    cudaGetSymbolAddress((void**)&pC,    g_bufC);
    cudaGetSymbolAddress((void**)&pE,    g_bufE);
    cudaGetSymbolAddress((void**)&pOff,  g_offb);
    cudaGetSymbolAddress((void**)&pAw,   g_awb);
    cudaGetSymbolAddress((void**)&pActh, g_acth);
    cudaGetSymbolAddress((void**)&pActl, g_actl);
    cudaGetSymbolAddress((void**)&pAct2h,g_act2h);
    cudaGetSymbolAddress((void**)&pAct2l,g_act2l);
    cudaGetSymbolAddress((void**)&pHh,   g_hh);
    cudaGetSymbolAddress((void**)&pHl,   g_hl);
    cudaGetSymbolAddress((void**)&pWh,   g_wh);
    cudaGetSymbolAddress((void**)&pWl,   g_wl);

    const int SMEM = 131072;   // 2 stages x 64KB
    static int s_attr = 0;
    if (!s_attr) {
        cudaFuncSetAttribute(k_mgemm, cudaFuncAttributeMaxDynamicSharedMemorySize, SMEM);
        s_attr = 1;
    }

    const int MT = TOT / 128;  // 392 row tiles

    // 1. LN1 + partition + diag -> bufA fp32, act pair (xw), act2 pair (q)
    k_ln1diag<<<TOT, 256>>>(x, mask, n1g, n1b);

    // 2. value = xw @ val_w + b -> bufC fp32
    k_wconv<<<(256 * 256 + 255) / 256, 256>>>(valw, 256, 256, 0);
    k_mgemm<<<dim3(2, MT), 256, SMEM>>>(pActh, pActl, pWh, pWl, valb, nullptr,
                                        pC, nullptr, nullptr, nullptr, nullptr,
                                        256, 256, 0);
    // 3. fused off/aw GEMM (N = 96 + 32 = 128)
    k_wconv<<<(256 * 96 + 255) / 256, 256>>>(offw, 256, 96, 0);
    k_wconv<<<(256 * 32 + 255) / 256, 256>>>(aww, 256, 32, 96);
    k_mgemm<<<dim3(1, MT), 256, SMEM>>>(pAct2h, pAct2l, pWh, pWl, offbi, awbi,
                                        pOff, pAw, nullptr, nullptr, nullptr,
                                        256, 0, 5);
    // 4. softmax over NP
    k_softmax4<<<(TOT * NHD + 255) / 256, 256>>>(pAw);
    // 5. deformable trilinear sampling -> act pair (D)
    k_sample<<<NWIN * NHD, 256>>>();
    // 6. attn out = D @ out_w + b -> bufE fp32
    k_wconv<<<(256 * 256 + 255) / 256, 256>>>(outw, 256, 256, 0);
    k_mgemm<<<dim3(2, MT), 256, SMEM>>>(pActh, pActl, pWh, pWl, outbi, nullptr,
                                        pE, nullptr, nullptr, nullptr, nullptr,
                                        256, 256, 0);
    // 7. act pair = LN(xw + attn) with anorm
    k_addln<<<TOT, 256>>>(ang, anb);
    // 8. window-reverse + residual: out = x + (act @ proj_w + b)
    k_wconv<<<(256 * 256 + 255) / 256, 256>>>(projw, 256, 256, 0);
    k_mgemm<<<dim3(2, MT), 256, SMEM>>>(pActh, pActl, pWh, pWl, projb, nullptr,
                                        out, nullptr, x, nullptr, nullptr,
                                        256, 256, 2);
    // 9. act pair = LN2(out)
    k_ln2<<<TOT, 256>>>(out, n2g, n2b);
    // 10. H = gelu(act @ fc1_w + b) -> bf16 pair
    k_wconv<<<(256 * 1024 + 255) / 256, 256>>>(fc1w, 256, 1024, 0);
    k_mgemm<<<dim3(8, MT), 256, SMEM>>>(pActh, pActl, pWh, pWl, fc1b, nullptr,
                                        nullptr, nullptr, nullptr, pHh, pHl,
                                        256, 1024, 4);
    // 11. out += H @ fc2_w + b
    k_wconv<<<(1024 * 256 + 255) / 256, 256>>>(fc2w, 1024, 256, 0);
    k_mgemm<<<dim3(2, MT), 256, SMEM>>>(pHh, pHl, pWh, pWl, fc2b, nullptr,
                                        out, nullptr, out, nullptr, nullptr,
                                        1024, 256, 3);
}

// round 13
// speedup vs baseline: 2.9926x; 1.5939x over previous
#include <cuda_runtime.h>
#include <cuda_fp16.h>
#include <math.h>
#include <stdint.h>

// Problem constants
#define CC    256
#define NTOK  98
#define NHD   8
#define HDIM  32
#define NWIN  512
#define TOT   (NWIN*NTOK)   // 50176
#define HHH   56
#define WWIDE 56

// ---------------- scratch (static device globals; no allocation) ----------------
__device__ __align__(16) float g_bufA[(size_t)TOT*CC];    // xw fp32 (addln)
__device__ __align__(16) float g_bufC[(size_t)TOT*CC];    // value fp32 (sampler)
__device__ __align__(16) float g_bufE[(size_t)TOT*CC];    // attn-out fp32 (addln)
__device__ __align__(16) float g_offb[(size_t)TOT*96];
__device__ __align__(16) float g_awb [(size_t)TOT*32];
__device__ __align__(16) __half g_acth [(size_t)TOT*CC];  // reused act (fp16 single)
__device__ __align__(16) __half g_act2h[(size_t)TOT*CC];  // q (fp16 single)
__device__ __align__(16) __half g_hh[(size_t)TOT*1024];   // gelu hidden (fp16 single)
__device__ __align__(16) __half g_wh[753664];             // all weights [N,K] fp16 hi
__device__ __align__(16) __half g_wl[753664];             // all weights [N,K] fp16 lo

// ---------------- PTX helpers (base-target features only) ----------------------
__device__ __forceinline__ uint32_t smem_u32(const void* p) {
    uint32_t a;
    asm("{ .reg .u64 t; cvta.to.shared.u64 t, %1; cvt.u32.u64 %0, t; }" : "=r"(a) : "l"(p));
    return a;
}
#define CPASYNC(sa, ga) asm volatile("cp.async.cg.shared.global [%0], [%1], 16;" :: "r"(sa), "l"(ga))
#define CPCOMMIT()      asm volatile("cp.async.commit_group;" ::: "memory")
#define CPWAIT1()       asm volatile("cp.async.wait_group 1;" ::: "memory")
#define CPWAIT0()       asm volatile("cp.async.wait_group 0;" ::: "memory")

__device__ __forceinline__ void ldsm_x4(uint32_t* r, uint32_t a) {
    asm volatile("ldmatrix.sync.aligned.m8n8.x4.shared.b16 {%0,%1,%2,%3}, [%4];"
                 : "=r"(r[0]), "=r"(r[1]), "=r"(r[2]), "=r"(r[3]) : "r"(a));
}
__device__ __forceinline__ void ldsm_x2(uint32_t* r, uint32_t a) {
    asm volatile("ldmatrix.sync.aligned.m8n8.x2.shared.b16 {%0,%1}, [%2];"
                 : "=r"(r[0]), "=r"(r[1]) : "r"(a));
}
__device__ __forceinline__ void mma16816(float* d, const uint32_t* a, const uint32_t* b) {
    asm volatile("mma.sync.aligned.m16n8k16.row.col.f32.f16.f16.f32 "
                 "{%0,%1,%2,%3}, {%4,%5,%6,%7}, {%8,%9}, {%0,%1,%2,%3};"
                 : "+f"(d[0]), "+f"(d[1]), "+f"(d[2]), "+f"(d[3])
                 : "r"(a[0]), "r"(a[1]), "r"(a[2]), "r"(a[3]), "r"(b[0]), "r"(b[1]));
}

// ---------------- small helpers ----------------
__device__ __forceinline__ float warp_sum(float v) {
    #pragma unroll
    for (int o = 16; o > 0; o >>= 1) v += __shfl_xor_sync(0xffffffffu, v, o);
    return v;
}
__device__ __forceinline__ float gelu_f(float x) {
    float x3 = x * x * x;
    return 0.5f * x * (1.f + tanhf(0.7978845608028654f * (x + 0.044715f * x3)));
}
__device__ __forceinline__ void hsplit(float v, __half* ph, __half* pl) {
    __half h = __float2half(v);
    *ph = h;
    *pl = __float2half(v - __half2float(h));
}

// ---------------- stage 1: LN1 + window partition + diag (warp per token) -------
__global__ void k_ln1diag(const float* __restrict__ x, const float* __restrict__ mask,
                          const float* __restrict__ g1, const float* __restrict__ b1)
{
    int warp = threadIdx.x >> 5, lane = threadIdx.x & 31;
    int t = blockIdx.x * 8 + warp;
    int win = t / NTOK, n = t % NTOK;
    int dwn = win >> 6, hwn = (win >> 3) & 7, wwn = win & 7;
    int wd = n / 49, rm = n % 49, wh = rm / 7, wx = rm % 7;
    int d = dwn * 2 + wd, h = hwn * 7 + wh, w = wwn * 7 + wx;
    size_t g = ((size_t)d * HHH + h) * WWIDE + w;

    const float4* xp = (const float4*)(x + g * CC) + lane * 2;
    float4 v0 = xp[0], v1 = xp[1];
    float s = v0.x + v0.y + v0.z + v0.w + v1.x + v1.y + v1.z + v1.w;
    float mean = warp_sum(s) * (1.f / 256.f);
    float vv[8] = { v0.x - mean, v0.y - mean, v0.z - mean, v0.w - mean,
                    v1.x - mean, v1.y - mean, v1.z - mean, v1.w - mean };
    float s2 = 0.f;
    #pragma unroll
    for (int i = 0; i < 8; i++) s2 += vv[i] * vv[i];
    float rstd = rsqrtf(warp_sum(s2) * (1.f / 256.f) + 1e-5f);

    float diag = 0.f;
    if (lane == 0) {
        const float* mrow = mask + ((size_t)win * NTOK + n) * NTOK;
        float m = mrow[(wd * 7 + wh) * 7 + wx];
        float zs = 0.f, ys = 0.f, xs = 0.f;
        for (int z = 0; z <= wd; z++) zs += mrow[z * 49 + wh * 7 + wx];
        for (int y = 0; y <= wh; y++) ys += mrow[wd * 49 + y * 7 + wx];
        for (int xq = 0; xq <= wx; xq++) xs += mrow[wd * 49 + wh * 7 + xq];
        const float INV_PI = 0.3183098861837907f;
        const float PI_F   = 3.14159265358979323846f;
        diag = m * (sinf(xs * m * INV_PI) + sinf(PI_F * ys * m * INV_PI) + zs * m * INV_PI);
    }
    diag = __shfl_sync(0xffffffffu, diag, 0);

    float4 ga = *((const float4*)(g1) + lane * 2), gb = *((const float4*)(g1) + lane * 2 + 1);
    float4 ba = *((const float4*)(b1) + lane * 2), bb = *((const float4*)(b1) + lane * 2 + 1);
    float gg[8] = { ga.x, ga.y, ga.z, ga.w, gb.x, gb.y, gb.z, gb.w };
    float bbv[8] = { ba.x, ba.y, ba.z, ba.w, bb.x, bb.y, bb.z, bb.w };

    size_t o = (size_t)t * CC + lane * 8;
    float xn[8];
    union { uint4 u; __half hx[8]; } p1, p2;
    #pragma unroll
    for (int i = 0; i < 8; i++) {
        xn[i] = vv[i] * rstd * gg[i] + bbv[i];
        p1.hx[i] = __float2half(xn[i]);
        p2.hx[i] = __float2half(xn[i] + diag);
    }
    *(float4*)(g_bufA + o)     = make_float4(xn[0], xn[1], xn[2], xn[3]);
    *(float4*)(g_bufA + o + 4) = make_float4(xn[4], xn[5], xn[6], xn[7]);
    *(uint4*)(g_acth + o)  = p1.u;
    *(uint4*)(g_act2h + o) = p2.u;
}

// ---------------- all-weights convert (+transpose to [N,K], fp16 hi/lo) ---------
__global__ void k_wconv_all(const float* __restrict__ w0, const float* __restrict__ w1,
                            const float* __restrict__ w2, const float* __restrict__ w3,
                            const float* __restrict__ w4, const float* __restrict__ w5,
                            const float* __restrict__ w6)
{
    int gid = blockIdx.x * 256 + threadIdx.x;
    const float* src; int base, Kd, Nd, e;
    if      (gid < 65536)  { src = w0; base = 0;      Kd = 256;  Nd = 256;  e = gid; }
    else if (gid < 90112)  { src = w1; base = 65536;  Kd = 256;  Nd = 96;   e = gid - 65536; }
    else if (gid < 98304)  { src = w2; base = 90112;  Kd = 256;  Nd = 32;   e = gid - 90112; }
    else if (gid < 163840) { src = w3; base = 98304;  Kd = 256;  Nd = 256;  e = gid - 98304; }
    else if (gid < 229376) { src = w4; base = 163840; Kd = 256;  Nd = 256;  e = gid - 163840; }
    else if (gid < 491520) { src = w5; base = 229376; Kd = 256;  Nd = 1024; e = gid - 229376; }
    else                   { src = w6; base = 491520; Kd = 1024; Nd = 256;  e = gid - 491520; }
    int k = e / Nd, n = e % Nd;
    float v = src[(size_t)k * Nd + n];
    size_t o = (size_t)base + (size_t)n * Kd + k;
    hsplit(v, &g_wh[o], &g_wl[o]);
}

// ---------------- fp16 2-term mma.sync GEMM -------------------------------------
// C[128,128-tile] = A[128,K] @ (Bh+Bl)^T[128,K]
// modes: 0 plain fp32 +bias; 2 winrev+residual; 3 residual add;
//        4 gelu -> fp16; 5 off/aw column split (N=128, n0=0)
__global__ void __launch_bounds__(256, 2)
k_hgemm(const __half* __restrict__ A,
        const __half* __restrict__ Bh, const __half* __restrict__ Bl,
        const float* __restrict__ bias, const float* __restrict__ bias2,
        float* __restrict__ out, float* __restrict__ out2,
        const float* __restrict__ aux, __half* __restrict__ outh,
        int K, int ldo, int mode)
{
    extern __shared__ char smem[];
    constexpr int STG = 49152;   // per-stage: A 16K | Bh 16K | Bl 16K
    int tid = threadIdx.x, wid = tid >> 5, lid = tid & 31;
    int row0 = blockIdx.y * 128;
    int n0 = blockIdx.x * 128;
    int nk = K >> 6;

    auto load_stage = [&](int ci, int s) {
        size_t ak = (size_t)row0 * K + ci * 64;
        size_t bk = (size_t)n0 * K + ci * 64;
        char* base = smem + s * STG;
        #pragma unroll
        for (int j = 0; j < 12; j++) {
            int idx = tid + j * 256;
            int seg = idx >> 10;            // 0:A 1:Bh 2:Bl
            int r = (idx >> 3) & 127;
            int c = idx & 7;
            uint32_t so = (uint32_t)(r * 128 + c * 16);
            so ^= (so >> 3) & 0x70;          // SW128 swizzle
            const __half* gp;
            if (seg == 0)      gp = A  + ak + (size_t)r * K + c * 8;
            else if (seg == 1) gp = Bh + bk + (size_t)r * K + c * 8;
            else               gp = Bl + bk + (size_t)r * K + c * 8;
            CPASYNC(smem_u32(base + seg * 16384 + so), gp);
        }
        CPCOMMIT();
    };

    float acc[4][4][4];
    #pragma unroll
    for (int a = 0; a < 4; a++)
        #pragma unroll
        for (int b = 0; b < 4; b++)
            #pragma unroll
            for (int c = 0; c < 4; c++) acc[a][b][c] = 0.f;

    int warp_m = wid >> 2, warp_n = wid & 3;     // 2 x 4 warp grid, warp tile 64x32
    int lrow_a = lid & 15, lcol_a = (lid >> 4) * 16;
    int l15 = lid & 15;
    int lrow_b = l15 & 7, lcol_b = (l15 >> 3) * 16;

    load_stage(0, 0);
    for (int i = 0; i < nk; i++) {
        if (i + 1 < nk) { load_stage(i + 1, (i + 1) & 1); CPWAIT1(); }
        else            { CPWAIT0(); }
        __syncthreads();
        char* sb = smem + (i & 1) * STG;
        uint32_t aS = smem_u32(sb), bH = aS + 16384, bL = aS + 32768;
        #pragma unroll
        for (int ks = 0; ks < 4; ks++) {
            int kb = ks * 32;                    // byte offset of 16-elem k group
            uint32_t af[4][4], bfh[4][2], bfl[4][2];
            #pragma unroll
            for (int mt = 0; mt < 4; mt++) {
                uint32_t o = (uint32_t)((warp_m * 64 + mt * 16 + lrow_a) * 128 + kb + lcol_a);
                o ^= (o >> 3) & 0x70;
                ldsm_x4(af[mt], aS + o);
            }
            #pragma unroll
            for (int nt = 0; nt < 4; nt++) {
                uint32_t o = (uint32_t)((warp_n * 32 + nt * 8 + lrow_b) * 128 + kb + lcol_b);
                o ^= (o >> 3) & 0x70;
                ldsm_x2(bfh[nt], bH + o);
                ldsm_x2(bfl[nt], bL + o);
            }
            #pragma unroll
            for (int mt = 0; mt < 4; mt++)
                #pragma unroll
                for (int nt = 0; nt < 4; nt++) {
                    mma16816(acc[mt][nt], af[mt], bfh[nt]);
                    mma16816(acc[mt][nt], af[mt], bfl[nt]);
                }
        }
        __syncthreads();
    }

    // ---- epilogue ----
    int lr = lid >> 2, lc = (lid & 3) * 2;
    #pragma unroll
    for (int mt = 0; mt < 4; mt++) {
        int rbase = row0 + warp_m * 64 + mt * 16 + lr;
        #pragma unroll
        for (int half = 0; half < 2; half++) {
            int r = rbase + half * 8;
            size_t g2 = 0;
            if (mode == 2) {
                int win = r / NTOK, n_ = r % NTOK;
                int dwn = win >> 6, hwn = (win >> 3) & 7, wwn = win & 7;
                int wd = n_ / 49, rm = n_ % 49, wh = rm / 7, wx = rm % 7;
                g2 = ((size_t)(dwn * 2 + wd) * HHH + (hwn * 7 + wh)) * WWIDE + (wwn * 7 + wx);
            }
            #pragma unroll
            for (int nt = 0; nt < 4; nt++) {
                int col = n0 + warp_n * 32 + nt * 8 + lc;
                float v0 = acc[mt][nt][half * 2 + 0];
                float v1 = acc[mt][nt][half * 2 + 1];
                if (mode == 5) {
                    if (col < 96) {
                        v0 += __ldg(bias + col);  v1 += __ldg(bias + col + 1);
                        *(float2*)(out + (size_t)r * 96 + col) = make_float2(v0, v1);
                    } else {
                        v0 += __ldg(bias2 + col - 96);  v1 += __ldg(bias2 + col - 95);
                        *(float2*)(out2 + (size_t)r * 32 + (col - 96)) = make_float2(v0, v1);
                    }
                } else if (mode == 4) {
                    float h0 = gelu_f(v0 + __ldg(bias + col));
                    float h1 = gelu_f(v1 + __ldg(bias + col + 1));
                    __half2 hp; hp.x = __float2half(h0); hp.y = __float2half(h1);
                    *(__half2*)(outh + (size_t)r * ldo + col) = hp;
                } else {
                    v0 += __ldg(bias + col);  v1 += __ldg(bias + col + 1);
                    if (mode == 0) {
                        *(float2*)(out + (size_t)r * ldo + col) = make_float2(v0, v1);
                    } else if (mode == 3) {
                        float2 a = *(const float2*)(aux + (size_t)r * ldo + col);
                        *(float2*)(out + (size_t)r * ldo + col) = make_float2(v0 + a.x, v1 + a.y);
                    } else { // mode 2
                        float2 a = *(const float2*)(aux + g2 * 256 + col);
                        *(float2*)(out + g2 * 256 + col) = make_float2(v0 + a.x, v1 + a.y);
                    }
                }
            }
        }
    }
}

// ---------------- softmax over NP=4 -------------------------------------------
__global__ void k_softmax4(float* __restrict__ a)
{
    int i = blockIdx.x * blockDim.x + threadIdx.x;
    if (i >= TOT * NHD) return;
    float* p = a + (size_t)i * 4;
    float l0 = p[0], l1 = p[1], l2 = p[2], l3 = p[3];
    float m = fmaxf(fmaxf(l0, l1), fmaxf(l2, l3));
    float e0 = __expf(l0 - m), e1 = __expf(l1 - m), e2 = __expf(l2 - m), e3 = __expf(l3 - m);
    float inv = 1.f / (e0 + e1 + e2 + e3);
    p[0] = e0 * inv; p[1] = e1 * inv; p[2] = e2 * inv; p[3] = e3 * inv;
}

// ---------------- deformable trilinear sampling -> act fp16 ---------------------
__global__ void k_sample()
{
    __shared__ float sval[NTOK * HDIM];
    int win  = blockIdx.x >> 3;
    int head = blockIdx.x & 7;

    for (int i = threadIdx.x; i < NTOK * HDIM; i += 256) {
        int s = i >> 5, dch = i & 31;
        sval[i] = g_bufC[((size_t)win * NTOK + s) * CC + head * HDIM + dch];
    }
    __syncthreads();

    int warp = threadIdx.x >> 5, lane = threadIdx.x & 31;
    for (int nn = warp; nn < NTOK; nn += 8) {
        int t = win * NTOK + nn;
        int z = nn / 49, rm = nn % 49, y = rm / 7, xq = rm % 7;
        float rx = (xq + 0.5f) / 7.0f;
        float ry = (y  + 0.5f) / 7.0f;
        float rz = (z  + 0.5f) / 2.0f;
        const float* offp = g_offb + (size_t)t * 96 + head * 12;
        const float* awp  = g_awb  + (size_t)t * 32 + head * 4;
        float tot = 0.f;
        #pragma unroll
        for (int p = 0; p < 4; p++) {
            float ox = offp[p * 3 + 0], oy = offp[p * 3 + 1], oz = offp[p * 3 + 2];
            float aw = awp[p];
            float px = (rx + ox * (1.f / 7.f)) * 7.f - 0.5f;
            float py = (ry + oy * (1.f / 7.f)) * 7.f - 0.5f;
            float pz = (rz + oz * (1.f / 2.f)) * 2.f - 0.5f;
            float x0 = floorf(px), y0 = floorf(py), z0 = floorf(pz);
            float samp = 0.f;
            #pragma unroll
            for (int dz = 0; dz < 2; dz++)
            #pragma unroll
            for (int dy = 0; dy < 2; dy++)
            #pragma unroll
            for (int dx = 0; dx < 2; dx++) {
                float xi = x0 + dx, yi = y0 + dy, zi = z0 + dz;
                float wgt = (1.f - fabsf(px - xi)) * (1.f - fabsf(py - yi)) * (1.f - fabsf(pz - zi));
                bool valid = (xi >= 0.f) && (xi < 7.f) && (yi >= 0.f) && (yi < 7.f) &&
                             (zi >= 0.f) && (zi < 2.f);
                if (valid) {
                    int idx = (((int)zi) * 7 + (int)yi) * 7 + (int)xi;
                    samp += wgt * sval[idx * HDIM + lane];
                }
            }
            tot += aw * samp;
        }
        g_acth[(size_t)t * CC + head * HDIM + lane] = __float2half(tot);
    }
}

// ---------------- residual + LN (anorm), warp per token -> act fp16 -------------
__global__ void k_addln(const float* __restrict__ gg, const float* __restrict__ bb)
{
    int warp = threadIdx.x >> 5, lane = threadIdx.x & 31;
    int t = blockIdx.x * 8 + warp;
    size_t o = (size_t)t * CC + lane * 8;
    float4 a0 = *(const float4*)(g_bufA + o),     a1 = *(const float4*)(g_bufA + o + 4);
    float4 e0 = *(const float4*)(g_bufE + o),     e1 = *(const float4*)(g_bufE + o + 4);
    float vv[8] = { a0.x + e0.x, a0.y + e0.y, a0.z + e0.z, a0.w + e0.w,
                    a1.x + e1.x, a1.y + e1.y, a1.z + e1.z, a1.w + e1.w };
    float s = 0.f;
    #pragma unroll
    for (int i = 0; i < 8; i++) s += vv[i];
    float mean = warp_sum(s) * (1.f / 256.f);
    float s2 = 0.f;
    #pragma unroll
    for (int i = 0; i < 8; i++) { vv[i] -= mean; s2 += vv[i] * vv[i]; }
    float rstd = rsqrtf(warp_sum(s2) * (1.f / 256.f) + 1e-5f);
    float4 ga = *((const float4*)(gg) + lane * 2), gb = *((const float4*)(gg) + lane * 2 + 1);
    float4 ba = *((const float4*)(bb) + lane * 2), b2 = *((const float4*)(bb) + lane * 2 + 1);
    float gv[8] = { ga.x, ga.y, ga.z, ga.w, gb.x, gb.y, gb.z, gb.w };
    float bv[8] = { ba.x, ba.y, ba.z, ba.w, b2.x, b2.y, b2.z, b2.w };
    union { uint4 u; __half hx[8]; } pk;
    #pragma unroll
    for (int i = 0; i < 8; i++) pk.hx[i] = __float2half(vv[i] * rstd * gv[i] + bv[i]);
    *(uint4*)(g_acth + o) = pk.u;
}

// ---------------- LN2, warp per token -> act fp16 -------------------------------
__global__ void k_ln2(const float* __restrict__ xin,
                      const float* __restrict__ gg, const float* __restrict__ bb)
{
    int warp = threadIdx.x >> 5, lane = threadIdx.x & 31;
    int t = blockIdx.x * 8 + warp;
    size_t o = (size_t)t * CC + lane * 8;
    float4 a0 = *(const float4*)(xin + o), a1 = *(const float4*)(xin + o + 4);
    float vv[8] = { a0.x, a0.y, a0.z, a0.w, a1.x, a1.y, a1.z, a1.w };
    float s = 0.f;
    #pragma unroll
    for (int i = 0; i < 8; i++) s += vv[i];
    float mean = warp_sum(s) * (1.f / 256.f);
    float s2 = 0.f;
    #pragma unroll
    for (int i = 0; i < 8; i++) { vv[i] -= mean; s2 += vv[i] * vv[i]; }
    float rstd = rsqrtf(warp_sum(s2) * (1.f / 256.f) + 1e-5f);
    float4 ga = *((const float4*)(gg) + lane * 2), gb = *((const float4*)(gg) + lane * 2 + 1);
    float4 ba = *((const float4*)(bb) + lane * 2), b2 = *((const float4*)(bb) + lane * 2 + 1);
    float gv[8] = { ga.x, ga.y, ga.z, ga.w, gb.x, gb.y, gb.z, gb.w };
    float bv[8] = { ba.x, ba.y, ba.z, ba.w, b2.x, b2.y, b2.z, b2.w };
    union { uint4 u; __half hx[8]; } pk;
    #pragma unroll
    for (int i = 0; i < 8; i++) pk.hx[i] = __float2half(vv[i] * rstd * gv[i] + bv[i]);
    *(uint4*)(g_acth + o) = pk.u;
}

// ---------------- launch --------------------------------------------------------
extern "C" void kernel_launch(void* const* d_in, const int* in_sizes, int n_in,
                              void* d_out, int out_size)
{
    (void)in_sizes; (void)n_in; (void)out_size;
    const float* x     = (const float*)d_in[0];
    const float* mask  = (const float*)d_in[1];
    const float* n1g   = (const float*)d_in[2];
    const float* n1b   = (const float*)d_in[3];
    const float* valw  = (const float*)d_in[4];
    const float* valb  = (const float*)d_in[5];
    const float* offw  = (const float*)d_in[6];
    const float* offbi = (const float*)d_in[7];
    const float* aww   = (const float*)d_in[8];
    const float* awbi  = (const float*)d_in[9];
    const float* outw  = (const float*)d_in[10];
    const float* outbi = (const float*)d_in[11];
    const float* ang   = (const float*)d_in[12];
    const float* anb   = (const float*)d_in[13];
    const float* projw = (const float*)d_in[14];
    const float* projb = (const float*)d_in[15];
    const float* n2g   = (const float*)d_in[16];
    const float* n2b   = (const float*)d_in[17];
    const float* fc1w  = (const float*)d_in[18];
    const float* fc1b  = (const float*)d_in[19];
    const float* fc2w  = (const float*)d_in[20];
    const float* fc2b  = (const float*)d_in[21];
    float* out = (float*)d_out;

    float *pC, *pE, *pOff, *pAw;
    __half *pActh, *pAct2h, *pHh, *pWh, *pWl;
    cudaGetSymbolAddress((void**)&pC,    g_bufC);
    cudaGetSymbolAddress((void**)&pE,    g_bufE);
    cudaGetSymbolAddress((void**)&pOff,  g_offb);
    cudaGetSymbolAddress((void**)&pAw,   g_awb);
    cudaGetSymbolAddress((void**)&pActh, g_acth);
    cudaGetSymbolAddress((void**)&pAct2h,g_act2h);
    cudaGetSymbolAddress((void**)&pHh,   g_hh);
    cudaGetSymbolAddress((void**)&pWh,   g_wh);
    cudaGetSymbolAddress((void**)&pWl,   g_wl);

    const int SMEM = 98304;   // 2 stages x 48KB
    cudaFuncSetAttribute(k_hgemm, cudaFuncAttributeMaxDynamicSharedMemorySize, SMEM);

    const int MT = TOT / 128;    // 392 row tiles
    const int LNG = TOT / 8;     // 6272 blocks, warp per token

    // 0. all weight converts in one launch
    k_wconv_all<<<2944, 256>>>(valw, offw, aww, outw, projw, fc1w, fc2w);
    // 1. LN1 + partition + diag -> bufA fp32, acth (xw), act2h (q)
    k_ln1diag<<<LNG, 256>>>(x, mask, n1g, n1b);
    // 2. value = xw @ val_w + b -> bufC fp32
    k_hgemm<<<dim3(2, MT), 256, SMEM>>>(pActh, pWh, pWl, valb, nullptr,
                                        pC, nullptr, nullptr, nullptr, 256, 256, 0);
    // 3. fused off/aw GEMM (N = 96 + 32 = 128)
    k_hgemm<<<dim3(1, MT), 256, SMEM>>>(pAct2h, pWh + 65536, pWl + 65536, offbi, awbi,
                                        pOff, pAw, nullptr, nullptr, 256, 0, 5);
    // 4. softmax over NP
    k_softmax4<<<(TOT * NHD + 255) / 256, 256>>>(pAw);
    // 5. deformable trilinear sampling -> acth (D)
    k_sample<<<NWIN * NHD, 256>>>();
    // 6. attn out = D @ out_w + b -> bufE fp32
    k_hgemm<<<dim3(2, MT), 256, SMEM>>>(pActh, pWh + 98304, pWl + 98304, outbi, nullptr,
                                        pE, nullptr, nullptr, nullptr, 256, 256, 0);
    // 7. acth = LN(xw + attn) with anorm
    k_addln<<<LNG, 256>>>(ang, anb);
    // 8. window-reverse + residual: out = x + (acth @ proj_w + b)
    k_hgemm<<<dim3(2, MT), 256, SMEM>>>(pActh, pWh + 163840, pWl + 163840, projb, nullptr,
                                        out, nullptr, x, nullptr, 256, 256, 2);
    // 9. acth = LN2(out)
    k_ln2<<<LNG, 256>>>(out, n2g, n2b);
    // 10. H = gelu(acth @ fc1_w + b) -> fp16
    k_hgemm<<<dim3(8, MT), 256, SMEM>>>(pActh, pWh + 229376, pWl + 229376, fc1b, nullptr,
                                        nullptr, nullptr, nullptr, pHh, 256, 1024, 4);
    // 11. out += H @ fc2_w + b
    k_hgemm<<<dim3(2, MT), 256, SMEM>>>(pHh, pWh + 491520, pWl + 491520, fc2b, nullptr,
                                        out, nullptr, out, nullptr, 1024, 256, 3);
}

// round 14
// speedup vs baseline: 3.6264x; 1.2118x over previous
#include <cuda_runtime.h>
#include <cuda_fp16.h>
#include <math.h>
#include <stdint.h>

// Problem constants
#define CC    256
#define NTOK  98
#define NHD   8
#define HDIM  32
#define NWIN  512
#define TOT   (NWIN*NTOK)   // 50176
#define HHH   56
#define WWIDE 56

// ---------------- scratch (static device globals; no allocation) ----------------
__device__ __align__(16) float g_bufA[(size_t)TOT*CC];    // xw fp32 (addln)
__device__ __align__(16) float g_bufC[(size_t)TOT*CC];    // value fp32 (sampler)
__device__ __align__(16) float g_bufE[(size_t)TOT*CC];    // attn-out fp32 (addln)
__device__ __align__(16) float g_offb[(size_t)TOT*96];
__device__ __align__(16) float g_awb [(size_t)TOT*32];
__device__ __align__(16) __half g_acth [(size_t)TOT*CC];  // reused act (fp16)
__device__ __align__(16) __half g_act2h[(size_t)TOT*CC];  // q (fp16)
__device__ __align__(16) __half g_hh[(size_t)TOT*1024];   // gelu hidden (fp16)
__device__ __align__(16) __half g_wh[753664];             // all weights [N,K] fp16

// ---------------- PTX helpers (base-target features only) ----------------------
__device__ __forceinline__ uint32_t smem_u32(const void* p) {
    uint32_t a;
    asm("{ .reg .u64 t; cvta.to.shared.u64 t, %1; cvt.u32.u64 %0, t; }" : "=r"(a) : "l"(p));
    return a;
}
#define CPASYNC(sa, ga) asm volatile("cp.async.cg.shared.global [%0], [%1], 16;" :: "r"(sa), "l"(ga))
#define CPCOMMIT()      asm volatile("cp.async.commit_group;" ::: "memory")
#define CPWAIT1()       asm volatile("cp.async.wait_group 1;" ::: "memory")
#define CPWAIT0()       asm volatile("cp.async.wait_group 0;" ::: "memory")

__device__ __forceinline__ void ldsm_x4(uint32_t* r, uint32_t a) {
    asm volatile("ldmatrix.sync.aligned.m8n8.x4.shared.b16 {%0,%1,%2,%3}, [%4];"
                 : "=r"(r[0]), "=r"(r[1]), "=r"(r[2]), "=r"(r[3]) : "r"(a));
}
__device__ __forceinline__ void ldsm_x2(uint32_t* r, uint32_t a) {
    asm volatile("ldmatrix.sync.aligned.m8n8.x2.shared.b16 {%0,%1}, [%2];"
                 : "=r"(r[0]), "=r"(r[1]) : "r"(a));
}
__device__ __forceinline__ void mma16816(float* d, const uint32_t* a, const uint32_t* b) {
    asm volatile("mma.sync.aligned.m16n8k16.row.col.f32.f16.f16.f32 "
                 "{%0,%1,%2,%3}, {%4,%5,%6,%7}, {%8,%9}, {%0,%1,%2,%3};"
                 : "+f"(d[0]), "+f"(d[1]), "+f"(d[2]), "+f"(d[3])
                 : "r"(a[0]), "r"(a[1]), "r"(a[2]), "r"(a[3]), "r"(b[0]), "r"(b[1]));
}

// ---------------- small helpers ----------------
__device__ __forceinline__ float warp_sum(float v) {
    #pragma unroll
    for (int o = 16; o > 0; o >>= 1) v += __shfl_xor_sync(0xffffffffu, v, o);
    return v;
}
__device__ __forceinline__ float gelu_f(float x) {
    float x3 = x * x * x;
    return 0.5f * x * (1.f + tanhf(0.7978845608028654f * (x + 0.044715f * x3)));
}

// ---------------- stage 1: LN1 + window partition + diag (warp per token) -------
__global__ void k_ln1diag(const float* __restrict__ x, const float* __restrict__ mask,
                          const float* __restrict__ g1, const float* __restrict__ b1)
{
    int warp = threadIdx.x >> 5, lane = threadIdx.x & 31;
    int t = blockIdx.x * 8 + warp;
    int win = t / NTOK, n = t % NTOK;
    int dwn = win >> 6, hwn = (win >> 3) & 7, wwn = win & 7;
    int wd = n / 49, rm = n % 49, wh = rm / 7, wx = rm % 7;
    int d = dwn * 2 + wd, h = hwn * 7 + wh, w = wwn * 7 + wx;
    size_t g = ((size_t)d * HHH + h) * WWIDE + w;

    const float4* xp = (const float4*)(x + g * CC) + lane * 2;
    float4 v0 = xp[0], v1 = xp[1];
    float s = v0.x + v0.y + v0.z + v0.w + v1.x + v1.y + v1.z + v1.w;
    float mean = warp_sum(s) * (1.f / 256.f);
    float vv[8] = { v0.x - mean, v0.y - mean, v0.z - mean, v0.w - mean,
                    v1.x - mean, v1.y - mean, v1.z - mean, v1.w - mean };
    float s2 = 0.f;
    #pragma unroll
    for (int i = 0; i < 8; i++) s2 += vv[i] * vv[i];
    float rstd = rsqrtf(warp_sum(s2) * (1.f / 256.f) + 1e-5f);

    float diag = 0.f;
    if (lane == 0) {
        const float* mrow = mask + ((size_t)win * NTOK + n) * NTOK;
        float m = mrow[(wd * 7 + wh) * 7 + wx];
        float zs = 0.f, ys = 0.f, xs = 0.f;
        for (int z = 0; z <= wd; z++) zs += mrow[z * 49 + wh * 7 + wx];
        for (int y = 0; y <= wh; y++) ys += mrow[wd * 49 + y * 7 + wx];
        for (int xq = 0; xq <= wx; xq++) xs += mrow[wd * 49 + wh * 7 + xq];
        const float INV_PI = 0.3183098861837907f;
        const float PI_F   = 3.14159265358979323846f;
        diag = m * (sinf(xs * m * INV_PI) + sinf(PI_F * ys * m * INV_PI) + zs * m * INV_PI);
    }
    diag = __shfl_sync(0xffffffffu, diag, 0);

    float4 ga = *((const float4*)(g1) + lane * 2), gb = *((const float4*)(g1) + lane * 2 + 1);
    float4 ba = *((const float4*)(b1) + lane * 2), bb = *((const float4*)(b1) + lane * 2 + 1);
    float gg[8] = { ga.x, ga.y, ga.z, ga.w, gb.x, gb.y, gb.z, gb.w };
    float bbv[8] = { ba.x, ba.y, ba.z, ba.w, bb.x, bb.y, bb.z, bb.w };

    size_t o = (size_t)t * CC + lane * 8;
    float xn[8];
    union { uint4 u; __half hx[8]; } p1, p2;
    #pragma unroll
    for (int i = 0; i < 8; i++) {
        xn[i] = vv[i] * rstd * gg[i] + bbv[i];
        p1.hx[i] = __float2half(xn[i]);
        p2.hx[i] = __float2half(xn[i] + diag);
    }
    *(float4*)(g_bufA + o)     = make_float4(xn[0], xn[1], xn[2], xn[3]);
    *(float4*)(g_bufA + o + 4) = make_float4(xn[4], xn[5], xn[6], xn[7]);
    *(uint4*)(g_acth + o)  = p1.u;
    *(uint4*)(g_act2h + o) = p2.u;
}

// ---------------- all-weights convert (+transpose to [N,K], fp16) ---------------
__global__ void k_wconv_all(const float* __restrict__ w0, const float* __restrict__ w1,
                            const float* __restrict__ w2, const float* __restrict__ w3,
                            const float* __restrict__ w4, const float* __restrict__ w5,
                            const float* __restrict__ w6)
{
    int gid = blockIdx.x * 256 + threadIdx.x;
    const float* src; int base, Kd, Nd, e;
    if      (gid < 65536)  { src = w0; base = 0;      Kd = 256;  Nd = 256;  e = gid; }
    else if (gid < 90112)  { src = w1; base = 65536;  Kd = 256;  Nd = 96;   e = gid - 65536; }
    else if (gid < 98304)  { src = w2; base = 90112;  Kd = 256;  Nd = 32;   e = gid - 90112; }
    else if (gid < 163840) { src = w3; base = 98304;  Kd = 256;  Nd = 256;  e = gid - 98304; }
    else if (gid < 229376) { src = w4; base = 163840; Kd = 256;  Nd = 256;  e = gid - 163840; }
    else if (gid < 491520) { src = w5; base = 229376; Kd = 256;  Nd = 1024; e = gid - 229376; }
    else                   { src = w6; base = 491520; Kd = 1024; Nd = 256;  e = gid - 491520; }
    int k = e / Nd, n = e % Nd;
    g_wh[(size_t)base + (size_t)n * Kd + k] = __float2half(src[(size_t)k * Nd + n]);
}

// ---------------- fp16 mma.sync GEMM, 3-stage cp.async pipeline ------------------
// C[128,128-tile] = A[128,K] @ B^T[128,K]
// modes: 0 plain fp32 +bias; 2 winrev+residual; 3 residual add;
//        4 gelu -> fp16; 5 off/aw column split (N=128, n0=0)
__global__ void __launch_bounds__(256, 2)
k_hgemm(const __half* __restrict__ A, const __half* __restrict__ B,
        const float* __restrict__ bias, const float* __restrict__ bias2,
        float* __restrict__ out, float* __restrict__ out2,
        const float* __restrict__ aux, __half* __restrict__ outh,
        int K, int ldo, int mode)
{
    extern __shared__ char smem[];
    constexpr int STG = 32768;   // per-stage: A 16K | B 16K
    int tid = threadIdx.x, wid = tid >> 5, lid = tid & 31;
    int row0 = blockIdx.y * 128;
    int n0 = blockIdx.x * 128;
    int nk = K >> 6;

    auto load_stage = [&](int ci, int s) {
        size_t ak = (size_t)row0 * K + ci * 64;
        size_t bk = (size_t)n0 * K + ci * 64;
        char* base = smem + s * STG;
        #pragma unroll
        for (int j = 0; j < 8; j++) {
            int idx = tid + j * 256;
            int seg = idx >> 10;            // 0:A 1:B
            int r = (idx >> 3) & 127;
            int c = idx & 7;
            uint32_t so = (uint32_t)(r * 128 + c * 16);
            so ^= (so >> 3) & 0x70;          // SW128 swizzle
            const __half* gp = seg ? (B + bk + (size_t)r * K + c * 8)
                                   : (A + ak + (size_t)r * K + c * 8);
            CPASYNC(smem_u32(base + seg * 16384 + so), gp);
        }
        CPCOMMIT();
    };

    float acc[4][4][4];
    #pragma unroll
    for (int a = 0; a < 4; a++)
        #pragma unroll
        for (int b = 0; b < 4; b++)
            #pragma unroll
            for (int c = 0; c < 4; c++) acc[a][b][c] = 0.f;

    int warp_m = wid >> 2, warp_n = wid & 3;     // 2 x 4 warp grid, warp tile 64x32
    int lrow_a = lid & 15, lcol_a = (lid >> 4) * 16;
    int l15 = lid & 15;
    int lrow_b = l15 & 7, lcol_b = (l15 >> 3) * 16;

    load_stage(0, 0);
    if (nk > 1) load_stage(1, 1);
    int sc = 0;                    // stage index of chunk i
    for (int i = 0; i < nk; i++) {
        if (i < nk - 1) CPWAIT1(); else CPWAIT0();
        __syncthreads();
        if (i + 2 < nk) {
            int sl = sc + 2; if (sl >= 3) sl -= 3;
            load_stage(i + 2, sl);
        }
        char* sb = smem + sc * STG;
        uint32_t aS = smem_u32(sb), bS = aS + 16384;
        #pragma unroll
        for (int ks = 0; ks < 4; ks++) {
            int kb = ks * 32;                    // byte offset of 16-elem k group
            uint32_t af[4][4], bf[4][2];
            #pragma unroll
            for (int mt = 0; mt < 4; mt++) {
                uint32_t o = (uint32_t)((warp_m * 64 + mt * 16 + lrow_a) * 128 + kb + lcol_a);
                o ^= (o >> 3) & 0x70;
                ldsm_x4(af[mt], aS + o);
            }
            #pragma unroll
            for (int nt = 0; nt < 4; nt++) {
                uint32_t o = (uint32_t)((warp_n * 32 + nt * 8 + lrow_b) * 128 + kb + lcol_b);
                o ^= (o >> 3) & 0x70;
                ldsm_x2(bf[nt], bS + o);
            }
            #pragma unroll
            for (int mt = 0; mt < 4; mt++)
                #pragma unroll
                for (int nt = 0; nt < 4; nt++)
                    mma16816(acc[mt][nt], af[mt], bf[nt]);
        }
        __syncthreads();
        if (++sc == 3) sc = 0;
    }

    // ---- epilogue ----
    int lr = lid >> 2, lc = (lid & 3) * 2;
    #pragma unroll
    for (int mt = 0; mt < 4; mt++) {
        int rbase = row0 + warp_m * 64 + mt * 16 + lr;
        #pragma unroll
        for (int half = 0; half < 2; half++) {
            int r = rbase + half * 8;
            size_t g2 = 0;
            if (mode == 2) {
                int win = r / NTOK, n_ = r % NTOK;
                int dwn = win >> 6, hwn = (win >> 3) & 7, wwn = win & 7;
                int wd = n_ / 49, rm = n_ % 49, wh = rm / 7, wx = rm % 7;
                g2 = ((size_t)(dwn * 2 + wd) * HHH + (hwn * 7 + wh)) * WWIDE + (wwn * 7 + wx);
            }
            #pragma unroll
            for (int nt = 0; nt < 4; nt++) {
                int col = n0 + warp_n * 32 + nt * 8 + lc;
                float v0 = acc[mt][nt][half * 2 + 0];
                float v1 = acc[mt][nt][half * 2 + 1];
                if (mode == 5) {
                    if (col < 96) {
                        v0 += __ldg(bias + col);  v1 += __ldg(bias + col + 1);
                        *(float2*)(out + (size_t)r * 96 + col) = make_float2(v0, v1);
                    } else {
                        v0 += __ldg(bias2 + col - 96);  v1 += __ldg(bias2 + col - 95);
                        *(float2*)(out2 + (size_t)r * 32 + (col - 96)) = make_float2(v0, v1);
                    }
                } else if (mode == 4) {
                    float h0 = gelu_f(v0 + __ldg(bias + col));
                    float h1 = gelu_f(v1 + __ldg(bias + col + 1));
                    __half2 hp; hp.x = __float2half(h0); hp.y = __float2half(h1);
                    *(__half2*)(outh + (size_t)r * ldo + col) = hp;
                } else {
                    v0 += __ldg(bias + col);  v1 += __ldg(bias + col + 1);
                    if (mode == 0) {
                        *(float2*)(out + (size_t)r * ldo + col) = make_float2(v0, v1);
                    } else if (mode == 3) {
                        float2 a = *(const float2*)(aux + (size_t)r * ldo + col);
                        *(float2*)(out + (size_t)r * ldo + col) = make_float2(v0 + a.x, v1 + a.y);
                    } else { // mode 2
                        float2 a = *(const float2*)(aux + g2 * 256 + col);
                        *(float2*)(out + g2 * 256 + col) = make_float2(v0 + a.x, v1 + a.y);
                    }
                }
            }
        }
    }
}

// ---------------- deformable sampling + fused softmax -> act fp16 ---------------
__global__ void k_sample()
{
    __shared__ float sval[NTOK * HDIM];
    int win  = blockIdx.x >> 3;
    int head = blockIdx.x & 7;

    for (int i = threadIdx.x; i < NTOK * HDIM; i += 256) {
        int s = i >> 5, dch = i & 31;
        sval[i] = g_bufC[((size_t)win * NTOK + s) * CC + head * HDIM + dch];
    }
    __syncthreads();

    int warp = threadIdx.x >> 5, lane = threadIdx.x & 31;
    for (int nn = warp; nn < NTOK; nn += 8) {
        int t = win * NTOK + nn;
        int z = nn / 49, rm = nn % 49, y = rm / 7, xq = rm % 7;
        float rx = (xq + 0.5f) / 7.0f;
        float ry = (y  + 0.5f) / 7.0f;
        float rz = (z  + 0.5f) / 2.0f;
        const float* offp = g_offb + (size_t)t * 96 + head * 12;
        const float* awp  = g_awb  + (size_t)t * 32 + head * 4;
        // fused softmax over the 4 logits
        float l0 = awp[0], l1 = awp[1], l2 = awp[2], l3 = awp[3];
        float mx = fmaxf(fmaxf(l0, l1), fmaxf(l2, l3));
        float e0 = __expf(l0 - mx), e1 = __expf(l1 - mx), e2 = __expf(l2 - mx), e3 = __expf(l3 - mx);
        float inv = 1.f / (e0 + e1 + e2 + e3);
        float awv[4] = { e0 * inv, e1 * inv, e2 * inv, e3 * inv };
        float tot = 0.f;
        #pragma unroll
        for (int p = 0; p < 4; p++) {
            float ox = offp[p * 3 + 0], oy = offp[p * 3 + 1], oz = offp[p * 3 + 2];
            float px = (rx + ox * (1.f / 7.f)) * 7.f - 0.5f;
            float py = (ry + oy * (1.f / 7.f)) * 7.f - 0.5f;
            float pz = (rz + oz * (1.f / 2.f)) * 2.f - 0.5f;
            float x0 = floorf(px), y0 = floorf(py), z0 = floorf(pz);
            float samp = 0.f;
            #pragma unroll
            for (int dz = 0; dz < 2; dz++)
            #pragma unroll
            for (int dy = 0; dy < 2; dy++)
            #pragma unroll
            for (int dx = 0; dx < 2; dx++) {
                float xi = x0 + dx, yi = y0 + dy, zi = z0 + dz;
                float wgt = (1.f - fabsf(px - xi)) * (1.f - fabsf(py - yi)) * (1.f - fabsf(pz - zi));
                bool valid = (xi >= 0.f) && (xi < 7.f) && (yi >= 0.f) && (yi < 7.f) &&
                             (zi >= 0.f) && (zi < 2.f);
                if (valid) {
                    int idx = (((int)zi) * 7 + (int)yi) * 7 + (int)xi;
                    samp += wgt * sval[idx * HDIM + lane];
                }
            }
            tot += awv[p] * samp;
        }
        g_acth[(size_t)t * CC + head * HDIM + lane] = __float2half(tot);
    }
}

// ---------------- residual + LN (anorm), warp per token -> act fp16 -------------
__global__ void k_addln(const float* __restrict__ gg, const float* __restrict__ bb)
{
    int warp = threadIdx.x >> 5, lane = threadIdx.x & 31;
    int t = blockIdx.x * 8 + warp;
    size_t o = (size_t)t * CC + lane * 8;
    float4 a0 = *(const float4*)(g_bufA + o),     a1 = *(const float4*)(g_bufA + o + 4);
    float4 e0 = *(const float4*)(g_bufE + o),     e1 = *(const float4*)(g_bufE + o + 4);
    float vv[8] = { a0.x + e0.x, a0.y + e0.y, a0.z + e0.z, a0.w + e0.w,
                    a1.x + e1.x, a1.y + e1.y, a1.z + e1.z, a1.w + e1.w };
    float s = 0.f;
    #pragma unroll
    for (int i = 0; i < 8; i++) s += vv[i];
    float mean = warp_sum(s) * (1.f / 256.f);
    float s2 = 0.f;
    #pragma unroll
    for (int i = 0; i < 8; i++) { vv[i] -= mean; s2 += vv[i] * vv[i]; }
    float rstd = rsqrtf(warp_sum(s2) * (1.f / 256.f) + 1e-5f);
    float4 ga = *((const float4*)(gg) + lane * 2), gb = *((const float4*)(gg) + lane * 2 + 1);
    float4 ba = *((const float4*)(bb) + lane * 2), b2 = *((const float4*)(bb) + lane * 2 + 1);
    float gv[8] = { ga.x, ga.y, ga.z, ga.w, gb.x, gb.y, gb.z, gb.w };
    float bv[8] = { ba.x, ba.y, ba.z, ba.w, b2.x, b2.y, b2.z, b2.w };
    union { uint4 u; __half hx[8]; } pk;
    #pragma unroll
    for (int i = 0; i < 8; i++) pk.hx[i] = __float2half(vv[i] * rstd * gv[i] + bv[i]);
    *(uint4*)(g_acth + o) = pk.u;
}

// ---------------- LN2, warp per token -> act fp16 -------------------------------
__global__ void k_ln2(const float* __restrict__ xin,
                      const float* __restrict__ gg, const float* __restrict__ bb)
{
    int warp = threadIdx.x >> 5, lane = threadIdx.x & 31;
    int t = blockIdx.x * 8 + warp;
    size_t o = (size_t)t * CC + lane * 8;
    float4 a0 = *(const float4*)(xin + o), a1 = *(const float4*)(xin + o + 4);
    float vv[8] = { a0.x, a0.y, a0.z, a0.w, a1.x, a1.y, a1.z, a1.w };
    float s = 0.f;
    #pragma unroll
    for (int i = 0; i < 8; i++) s += vv[i];
    float mean = warp_sum(s) * (1.f / 256.f);
    float s2 = 0.f;
    #pragma unroll
    for (int i = 0; i < 8; i++) { vv[i] -= mean; s2 += vv[i] * vv[i]; }
    float rstd = rsqrtf(warp_sum(s2) * (1.f / 256.f) + 1e-5f);
    float4 ga = *((const float4*)(gg) + lane * 2), gb = *((const float4*)(gg) + lane * 2 + 1);
    float4 ba = *((const float4*)(bb) + lane * 2), b2 = *((const float4*)(bb) + lane * 2 + 1);
    float gv[8] = { ga.x, ga.y, ga.z, ga.w, gb.x, gb.y, gb.z, gb.w };
    float bv[8] = { ba.x, ba.y, ba.z, ba.w, b2.x, b2.y, b2.z, b2.w };
    union { uint4 u; __half hx[8]; } pk;
    #pragma unroll
    for (int i = 0; i < 8; i++) pk.hx[i] = __float2half(vv[i] * rstd * gv[i] + bv[i]);
    *(uint4*)(g_acth + o) = pk.u;
}

// ---------------- launch --------------------------------------------------------
extern "C" void kernel_launch(void* const* d_in, const int* in_sizes, int n_in,
                              void* d_out, int out_size)
{
    (void)in_sizes; (void)n_in; (void)out_size;
    const float* x     = (const float*)d_in[0];
    const float* mask  = (const float*)d_in[1];
    const float* n1g   = (const float*)d_in[2];
    const float* n1b   = (const float*)d_in[3];
    const float* valw  = (const float*)d_in[4];
    const float* valb  = (const float*)d_in[5];
    const float* offw  = (const float*)d_in[6];
    const float* offbi = (const float*)d_in[7];
    const float* aww   = (const float*)d_in[8];
    const float* awbi  = (const float*)d_in[9];
    const float* outw  = (const float*)d_in[10];
    const float* outbi = (const float*)d_in[11];
    const float* ang   = (const float*)d_in[12];
    const float* anb   = (const float*)d_in[13];
    const float* projw = (const float*)d_in[14];
    const float* projb = (const float*)d_in[15];
    const float* n2g   = (const float*)d_in[16];
    const float* n2b   = (const float*)d_in[17];
    const float* fc1w  = (const float*)d_in[18];
    const float* fc1b  = (const float*)d_in[19];
    const float* fc2w  = (const float*)d_in[20];
    const float* fc2b  = (const float*)d_in[21];
    float* out = (float*)d_out;

    float *pC, *pE, *pOff, *pAw;
    __half *pActh, *pAct2h, *pHh, *pWh;
    cudaGetSymbolAddress((void**)&pC,    g_bufC);
    cudaGetSymbolAddress((void**)&pE,    g_bufE);
    cudaGetSymbolAddress((void**)&pOff,  g_offb);
    cudaGetSymbolAddress((void**)&pAw,   g_awb);
    cudaGetSymbolAddress((void**)&pActh, g_acth);
    cudaGetSymbolAddress((void**)&pAct2h,g_act2h);
    cudaGetSymbolAddress((void**)&pHh,   g_hh);
    cudaGetSymbolAddress((void**)&pWh,   g_wh);

    const int SMEM = 98304;   // 3 stages x 32KB
    cudaFuncSetAttribute(k_hgemm, cudaFuncAttributeMaxDynamicSharedMemorySize, SMEM);

    const int MT = TOT / 128;    // 392 row tiles
    const int LNG = TOT / 8;     // warp per token

    // 0. all weight converts in one launch
    k_wconv_all<<<2944, 256>>>(valw, offw, aww, outw, projw, fc1w, fc2w);
    // 1. LN1 + partition + diag -> bufA fp32, acth (xw), act2h (q)
    k_ln1diag<<<LNG, 256>>>(x, mask, n1g, n1b);
    // 2. value = xw @ val_w + b -> bufC fp32
    k_hgemm<<<dim3(2, MT), 256, SMEM>>>(pActh, pWh, valb, nullptr,
                                        pC, nullptr, nullptr, nullptr, 256, 256, 0);
    // 3. fused off/aw GEMM (N = 96 + 32 = 128)
    k_hgemm<<<dim3(1, MT), 256, SMEM>>>(pAct2h, pWh + 65536, offbi, awbi,
                                        pOff, pAw, nullptr, nullptr, 256, 0, 5);
    // 4. deformable sampling (softmax fused) -> acth (D)
    k_sample<<<NWIN * NHD, 256>>>();
    // 5. attn out = D @ out_w + b -> bufE fp32
    k_hgemm<<<dim3(2, MT), 256, SMEM>>>(pActh, pWh + 98304, outbi, nullptr,
                                        pE, nullptr, nullptr, nullptr, 256, 256, 0);
    // 6. acth = LN(xw + attn) with anorm
    k_addln<<<LNG, 256>>>(ang, anb);
    // 7. window-reverse + residual: out = x + (acth @ proj_w + b)
    k_hgemm<<<dim3(2, MT), 256, SMEM>>>(pActh, pWh + 163840, projb, nullptr,
                                        out, nullptr, x, nullptr, 256, 256, 2);
    // 8. acth = LN2(out)
    k_ln2<<<LNG, 256>>>(out, n2g, n2b);
    // 9. H = gelu(acth @ fc1_w + b) -> fp16
    k_hgemm<<<dim3(8, MT), 256, SMEM>>>(pActh, pWh + 229376, fc1b, nullptr,
                                        nullptr, nullptr, nullptr, pHh, 256, 1024, 4);
    // 10. out += H @ fc2_w + b
    k_hgemm<<<dim3(2, MT), 256, SMEM>>>(pHh, pWh + 491520, fc2b, nullptr,
                                        out, nullptr, out, nullptr, 1024, 256, 3);
}

// round 15
// speedup vs baseline: 3.6501x; 1.0065x over previous
#include <cuda_runtime.h>
#include <cuda_fp16.h>
#include <math.h>
#include <stdint.h>

// Problem constants
#define CC    256
#define NTOK  98
#define NHD   8
#define HDIM  32
#define NWIN  512
#define TOT   (NWIN*NTOK)   // 50176
#define HHH   56
#define WWIDE 56

// ---------------- scratch (static device globals; no allocation) ----------------
__device__ __align__(16) float g_offb[(size_t)TOT*96];
__device__ __align__(16) float g_awb [(size_t)TOT*32];
__device__ __align__(16) __half g_acth [(size_t)TOT*CC];  // xw -> LN(x+attn) -> LN2
__device__ __align__(16) __half g_act2h[(size_t)TOT*CC];  // q -> sampled D
__device__ __align__(16) __half g_hh[(size_t)TOT*1024];   // [0,TC): value, [TC,2TC): attn; later fc1 hidden
__device__ __align__(16) __half g_wh[753664];             // all weights [N,K] fp16

// ---------------- PTX helpers (base-target features only) ----------------------
__device__ __forceinline__ uint32_t smem_u32(const void* p) {
    uint32_t a;
    asm("{ .reg .u64 t; cvta.to.shared.u64 t, %1; cvt.u32.u64 %0, t; }" : "=r"(a) : "l"(p));
    return a;
}
#define CPASYNC(sa, ga) asm volatile("cp.async.cg.shared.global [%0], [%1], 16;" :: "r"(sa), "l"(ga))
#define CPCOMMIT()      asm volatile("cp.async.commit_group;" ::: "memory")
#define CPWAIT1()       asm volatile("cp.async.wait_group 1;" ::: "memory")
#define CPWAIT0()       asm volatile("cp.async.wait_group 0;" ::: "memory")

__device__ __forceinline__ void ldsm_x4(uint32_t* r, uint32_t a) {
    asm volatile("ldmatrix.sync.aligned.m8n8.x4.shared.b16 {%0,%1,%2,%3}, [%4];"
                 : "=r"(r[0]), "=r"(r[1]), "=r"(r[2]), "=r"(r[3]) : "r"(a));
}
__device__ __forceinline__ void ldsm_x2(uint32_t* r, uint32_t a) {
    asm volatile("ldmatrix.sync.aligned.m8n8.x2.shared.b16 {%0,%1}, [%2];"
                 : "=r"(r[0]), "=r"(r[1]) : "r"(a));
}
__device__ __forceinline__ void mma16816(float* d, const uint32_t* a, const uint32_t* b) {
    asm volatile("mma.sync.aligned.m16n8k16.row.col.f32.f16.f16.f32 "
                 "{%0,%1,%2,%3}, {%4,%5,%6,%7}, {%8,%9}, {%0,%1,%2,%3};"
                 : "+f"(d[0]), "+f"(d[1]), "+f"(d[2]), "+f"(d[3])
                 : "r"(a[0]), "r"(a[1]), "r"(a[2]), "r"(a[3]), "r"(b[0]), "r"(b[1]));
}

// ---------------- small helpers ----------------
__device__ __forceinline__ float warp_sum(float v) {
    #pragma unroll
    for (int o = 16; o > 0; o >>= 1) v += __shfl_xor_sync(0xffffffffu, v, o);
    return v;
}
__device__ __forceinline__ float gelu_f(float x) {
    float x3 = x * x * x;
    return 0.5f * x * (1.f + tanhf(0.7978845608028654f * (x + 0.044715f * x3)));
}

// ---------------- stage 1: LN1 + window partition + diag (warp per token) -------
__global__ void k_ln1diag(const float* __restrict__ x, const float* __restrict__ mask,
                          const float* __restrict__ g1, const float* __restrict__ b1)
{
    int warp = threadIdx.x >> 5, lane = threadIdx.x & 31;
    int t = blockIdx.x * 8 + warp;
    int win = t / NTOK, n = t % NTOK;
    int dwn = win >> 6, hwn = (win >> 3) & 7, wwn = win & 7;
    int wd = n / 49, rm = n % 49, wh = rm / 7, wx = rm % 7;
    int d = dwn * 2 + wd, h = hwn * 7 + wh, w = wwn * 7 + wx;
    size_t g = ((size_t)d * HHH + h) * WWIDE + w;

    const float4* xp = (const float4*)(x + g * CC) + lane * 2;
    float4 v0 = xp[0], v1 = xp[1];
    float s = v0.x + v0.y + v0.z + v0.w + v1.x + v1.y + v1.z + v1.w;
    float mean = warp_sum(s) * (1.f / 256.f);
    float vv[8] = { v0.x - mean, v0.y - mean, v0.z - mean, v0.w - mean,
                    v1.x - mean, v1.y - mean, v1.z - mean, v1.w - mean };
    float s2 = 0.f;
    #pragma unroll
    for (int i = 0; i < 8; i++) s2 += vv[i] * vv[i];
    float rstd = rsqrtf(warp_sum(s2) * (1.f / 256.f) + 1e-5f);

    float diag = 0.f;
    if (lane == 0) {
        const float* mrow = mask + ((size_t)win * NTOK + n) * NTOK;
        float m = mrow[(wd * 7 + wh) * 7 + wx];
        float zs = 0.f, ys = 0.f, xs = 0.f;
        for (int z = 0; z <= wd; z++) zs += mrow[z * 49 + wh * 7 + wx];
        for (int y = 0; y <= wh; y++) ys += mrow[wd * 49 + y * 7 + wx];
        for (int xq = 0; xq <= wx; xq++) xs += mrow[wd * 49 + wh * 7 + xq];
        const float INV_PI = 0.3183098861837907f;
        const float PI_F   = 3.14159265358979323846f;
        diag = m * (sinf(xs * m * INV_PI) + sinf(PI_F * ys * m * INV_PI) + zs * m * INV_PI);
    }
    diag = __shfl_sync(0xffffffffu, diag, 0);

    float4 ga = *((const float4*)(g1) + lane * 2), gb = *((const float4*)(g1) + lane * 2 + 1);
    float4 ba = *((const float4*)(b1) + lane * 2), bb = *((const float4*)(b1) + lane * 2 + 1);
    float gg[8] = { ga.x, ga.y, ga.z, ga.w, gb.x, gb.y, gb.z, gb.w };
    float bbv[8] = { ba.x, ba.y, ba.z, ba.w, bb.x, bb.y, bb.z, bb.w };

    size_t o = (size_t)t * CC + lane * 8;
    union { uint4 u; __half hx[8]; } p1, p2;
    #pragma unroll
    for (int i = 0; i < 8; i++) {
        float xn = vv[i] * rstd * gg[i] + bbv[i];
        p1.hx[i] = __float2half(xn);
        p2.hx[i] = __float2half(xn + diag);
    }
    *(uint4*)(g_acth + o)  = p1.u;
    *(uint4*)(g_act2h + o) = p2.u;
}

// ---------------- all-weights convert (+transpose to [N,K], fp16) ---------------
__global__ void k_wconv_all(const float* __restrict__ w0, const float* __restrict__ w1,
                            const float* __restrict__ w2, const float* __restrict__ w3,
                            const float* __restrict__ w4, const float* __restrict__ w5,
                            const float* __restrict__ w6)
{
    int gid = blockIdx.x * 256 + threadIdx.x;
    const float* src; int base, Kd, Nd, e;
    if      (gid < 65536)  { src = w0; base = 0;      Kd = 256;  Nd = 256;  e = gid; }
    else if (gid < 90112)  { src = w1; base = 65536;  Kd = 256;  Nd = 96;   e = gid - 65536; }
    else if (gid < 98304)  { src = w2; base = 90112;  Kd = 256;  Nd = 32;   e = gid - 90112; }
    else if (gid < 163840) { src = w3; base = 98304;  Kd = 256;  Nd = 256;  e = gid - 98304; }
    else if (gid < 229376) { src = w4; base = 163840; Kd = 256;  Nd = 256;  e = gid - 163840; }
    else if (gid < 491520) { src = w5; base = 229376; Kd = 256;  Nd = 1024; e = gid - 229376; }
    else                   { src = w6; base = 491520; Kd = 1024; Nd = 256;  e = gid - 491520; }
    int k = e / Nd, n = e % Nd;
    g_wh[(size_t)base + (size_t)n * Kd + k] = __float2half(src[(size_t)k * Nd + n]);
}

// ---------------- fp16 mma.sync GEMM, 3-stage cp.async pipeline ------------------
// modes: 2 winrev+residual; 3 residual add; 4 gelu->fp16; 5 off/aw split;
//        6 plain fp16 store; 7 fused dispatch (bx<2: mode6 A/B, bx==2: mode5 A2/B2)
__global__ void __launch_bounds__(256, 2)
k_hgemm(const __half* __restrict__ A, const __half* __restrict__ B,
        const __half* __restrict__ A2, const __half* __restrict__ B2,
        const float* __restrict__ bias, const float* __restrict__ bias2,
        const float* __restrict__ bias3,
        float* __restrict__ out, float* __restrict__ out2,
        const float* __restrict__ aux, __half* __restrict__ outh,
        int K, int ldo, int mode)
{
    extern __shared__ char smem[];
    constexpr int STG = 32768;   // per-stage: A 16K | B 16K
    int tid = threadIdx.x, wid = tid >> 5, lid = tid & 31;
    int row0 = blockIdx.y * 128;
    int n0 = blockIdx.x * 128;
    int nk = K >> 6;

    if (mode == 7) {
        if (blockIdx.x == 2) { A = A2; B = B2; bias = bias2; bias2 = bias3; n0 = 0; mode = 5; }
        else                 { mode = 6; }
    }

    auto load_stage = [&](int ci, int s) {
        size_t ak = (size_t)row0 * K + ci * 64;
        size_t bk = (size_t)n0 * K + ci * 64;
        char* base = smem + s * STG;
        #pragma unroll
        for (int j = 0; j < 8; j++) {
            int idx = tid + j * 256;
            int seg = idx >> 10;            // 0:A 1:B
            int r = (idx >> 3) & 127;
            int c = idx & 7;
            uint32_t so = (uint32_t)(r * 128 + c * 16);
            so ^= (so >> 3) & 0x70;          // SW128 swizzle
            const __half* gp = seg ? (B + bk + (size_t)r * K + c * 8)
                                   : (A + ak + (size_t)r * K + c * 8);
            CPASYNC(smem_u32(base + seg * 16384 + so), gp);
        }
        CPCOMMIT();
    };

    float acc[4][4][4];
    #pragma unroll
    for (int a = 0; a < 4; a++)
        #pragma unroll
        for (int b = 0; b < 4; b++)
            #pragma unroll
            for (int c = 0; c < 4; c++) acc[a][b][c] = 0.f;

    int warp_m = wid >> 2, warp_n = wid & 3;     // 2 x 4 warp grid, warp tile 64x32
    int lrow_a = lid & 15, lcol_a = (lid >> 4) * 16;
    int l15 = lid & 15;
    int lrow_b = l15 & 7, lcol_b = (l15 >> 3) * 16;

    load_stage(0, 0);
    if (nk > 1) load_stage(1, 1);
    int sc = 0;                    // stage index of chunk i
    for (int i = 0; i < nk; i++) {
        if (i < nk - 1) CPWAIT1(); else CPWAIT0();
        __syncthreads();
        if (i + 2 < nk) {
            int sl = sc + 2; if (sl >= 3) sl -= 3;
            load_stage(i + 2, sl);
        }
        char* sb = smem + sc * STG;
        uint32_t aS = smem_u32(sb), bS = aS + 16384;
        #pragma unroll
        for (int ks = 0; ks < 4; ks++) {
            int kb = ks * 32;                    // byte offset of 16-elem k group
            uint32_t af[4][4], bf[4][2];
            #pragma unroll
            for (int mt = 0; mt < 4; mt++) {
                uint32_t o = (uint32_t)((warp_m * 64 + mt * 16 + lrow_a) * 128 + kb + lcol_a);
                o ^= (o >> 3) & 0x70;
                ldsm_x4(af[mt], aS + o);
            }
            #pragma unroll
            for (int nt = 0; nt < 4; nt++) {
                uint32_t o = (uint32_t)((warp_n * 32 + nt * 8 + lrow_b) * 128 + kb + lcol_b);
                o ^= (o >> 3) & 0x70;
                ldsm_x2(bf[nt], bS + o);
            }
            #pragma unroll
            for (int mt = 0; mt < 4; mt++)
                #pragma unroll
                for (int nt = 0; nt < 4; nt++)
                    mma16816(acc[mt][nt], af[mt], bf[nt]);
        }
        if (++sc == 3) sc = 0;
        // note: no trailing __syncthreads — top barrier orders slot reuse (3 stages)
    }

    // ---- epilogue ----
    int lr = lid >> 2, lc = (lid & 3) * 2;
    #pragma unroll
    for (int mt = 0; mt < 4; mt++) {
        int rbase = row0 + warp_m * 64 + mt * 16 + lr;
        #pragma unroll
        for (int half = 0; half < 2; half++) {
            int r = rbase + half * 8;
            size_t g2 = 0;
            if (mode == 2) {
                int win = r / NTOK, n_ = r % NTOK;
                int dwn = win >> 6, hwn = (win >> 3) & 7, wwn = win & 7;
                int wd = n_ / 49, rm = n_ % 49, wh = rm / 7, wx = rm % 7;
                g2 = ((size_t)(dwn * 2 + wd) * HHH + (hwn * 7 + wh)) * WWIDE + (wwn * 7 + wx);
            }
            #pragma unroll
            for (int nt = 0; nt < 4; nt++) {
                int col = n0 + warp_n * 32 + nt * 8 + lc;
                float v0 = acc[mt][nt][half * 2 + 0];
                float v1 = acc[mt][nt][half * 2 + 1];
                if (mode == 5) {
                    if (col < 96) {
                        v0 += __ldg(bias + col);  v1 += __ldg(bias + col + 1);
                        *(float2*)(out + (size_t)r * 96 + col) = make_float2(v0, v1);
                    } else {
                        v0 += __ldg(bias2 + col - 96);  v1 += __ldg(bias2 + col - 95);
                        *(float2*)(out2 + (size_t)r * 32 + (col - 96)) = make_float2(v0, v1);
                    }
                } else if (mode == 4 || mode == 6) {
                    float h0 = v0 + __ldg(bias + col);
                    float h1 = v1 + __ldg(bias + col + 1);
                    if (mode == 4) { h0 = gelu_f(h0); h1 = gelu_f(h1); }
                    __half2 hp; hp.x = __float2half(h0); hp.y = __float2half(h1);
                    *(__half2*)(outh + (size_t)r * ldo + col) = hp;
                } else {
                    v0 += __ldg(bias + col);  v1 += __ldg(bias + col + 1);
                    if (mode == 3) {
                        float2 a = *(const float2*)(aux + (size_t)r * ldo + col);
                        *(float2*)(out + (size_t)r * ldo + col) = make_float2(v0 + a.x, v1 + a.y);
                    } else { // mode 2
                        float2 a = *(const float2*)(aux + g2 * 256 + col);
                        *(float2*)(out + g2 * 256 + col) = make_float2(v0 + a.x, v1 + a.y);
                    }
                }
            }
        }
    }
}

// ---------------- deformable sampling + fused softmax -> D fp16 -----------------
__global__ void k_sample()
{
    __shared__ float sval[NTOK * HDIM];
    int win  = blockIdx.x >> 3;
    int head = blockIdx.x & 7;

    const __half* vplane = g_hh;   // value plane
    for (int i = threadIdx.x; i < NTOK * HDIM; i += 256) {
        int s = i >> 5, dch = i & 31;
        sval[i] = __half2float(vplane[((size_t)win * NTOK + s) * CC + head * HDIM + dch]);
    }
    __syncthreads();

    int warp = threadIdx.x >> 5, lane = threadIdx.x & 31;
    for (int nn = warp; nn < NTOK; nn += 8) {
        int t = win * NTOK + nn;
        int z = nn / 49, rm = nn % 49, y = rm / 7, xq = rm % 7;
        float rx = (xq + 0.5f) / 7.0f;
        float ry = (y  + 0.5f) / 7.0f;
        float rz = (z  + 0.5f) / 2.0f;
        const float* offp = g_offb + (size_t)t * 96 + head * 12;
        const float* awp  = g_awb  + (size_t)t * 32 + head * 4;
        float l0 = awp[0], l1 = awp[1], l2 = awp[2], l3 = awp[3];
        float mx = fmaxf(fmaxf(l0, l1), fmaxf(l2, l3));
        float e0 = __expf(l0 - mx), e1 = __expf(l1 - mx), e2 = __expf(l2 - mx), e3 = __expf(l3 - mx);
        float inv = 1.f / (e0 + e1 + e2 + e3);
        float awv[4] = { e0 * inv, e1 * inv, e2 * inv, e3 * inv };
        float tot = 0.f;
        #pragma unroll
        for (int p = 0; p < 4; p++) {
            float ox = offp[p * 3 + 0], oy = offp[p * 3 + 1], oz = offp[p * 3 + 2];
            float px = (rx + ox * (1.f / 7.f)) * 7.f - 0.5f;
            float py = (ry + oy * (1.f / 7.f)) * 7.f - 0.5f;
            float pz = (rz + oz * (1.f / 2.f)) * 2.f - 0.5f;
            float x0 = floorf(px), y0 = floorf(py), z0 = floorf(pz);
            float samp = 0.f;
            #pragma unroll
            for (int dz = 0; dz < 2; dz++)
            #pragma unroll
            for (int dy = 0; dy < 2; dy++)
            #pragma unroll
            for (int dx = 0; dx < 2; dx++) {
                float xi = x0 + dx, yi = y0 + dy, zi = z0 + dz;
                float wgt = (1.f - fabsf(px - xi)) * (1.f - fabsf(py - yi)) * (1.f - fabsf(pz - zi));
                bool valid = (xi >= 0.f) && (xi < 7.f) && (yi >= 0.f) && (yi < 7.f) &&
                             (zi >= 0.f) && (zi < 2.f);
                if (valid) {
                    int idx = (((int)zi) * 7 + (int)yi) * 7 + (int)xi;
                    samp += wgt * sval[idx * HDIM + lane];
                }
            }
            tot += awv[p] * samp;
        }
        g_act2h[(size_t)t * CC + head * HDIM + lane] = __float2half(tot);
    }
}

// ---------------- residual(xw fp16 + attn fp16) + LN (anorm) -> acth ------------
__global__ void k_addln(const float* __restrict__ gg, const float* __restrict__ bb)
{
    int warp = threadIdx.x >> 5, lane = threadIdx.x & 31;
    int t = blockIdx.x * 8 + warp;
    size_t o = (size_t)t * CC + lane * 8;
    union { uint4 u; __half h[8]; } xa, ea;
    xa.u = *(const uint4*)(g_acth + o);
    ea.u = *(const uint4*)(g_hh + (size_t)TOT * CC + o);
    float vv[8];
    #pragma unroll
    for (int i = 0; i < 8; i++) vv[i] = __half2float(xa.h[i]) + __half2float(ea.h[i]);
    float s = 0.f;
    #pragma unroll
    for (int i = 0; i < 8; i++) s += vv[i];
    float mean = warp_sum(s) * (1.f / 256.f);
    float s2 = 0.f;
    #pragma unroll
    for (int i = 0; i < 8; i++) { vv[i] -= mean; s2 += vv[i] * vv[i]; }
    float rstd = rsqrtf(warp_sum(s2) * (1.f / 256.f) + 1e-5f);
    float4 ga = *((const float4*)(gg) + lane * 2), gb = *((const float4*)(gg) + lane * 2 + 1);
    float4 ba = *((const float4*)(bb) + lane * 2), b2 = *((const float4*)(bb) + lane * 2 + 1);
    float gv[8] = { ga.x, ga.y, ga.z, ga.w, gb.x, gb.y, gb.z, gb.w };
    float bv[8] = { ba.x, ba.y, ba.z, ba.w, b2.x, b2.y, b2.z, b2.w };
    union { uint4 u; __half hx[8]; } pk;
    #pragma unroll
    for (int i = 0; i < 8; i++) pk.hx[i] = __float2half(vv[i] * rstd * gv[i] + bv[i]);
    *(uint4*)(g_acth + o) = pk.u;
}

// ---------------- LN2, warp per token -> acth fp16 ------------------------------
__global__ void k_ln2(const float* __restrict__ xin,
                      const float* __restrict__ gg, const float* __restrict__ bb)
{
    int warp = threadIdx.x >> 5, lane = threadIdx.x & 31;
    int t = blockIdx.x * 8 + warp;
    size_t o = (size_t)t * CC + lane * 8;
    float4 a0 = *(const float4*)(xin + o), a1 = *(const float4*)(xin + o + 4);
    float vv[8] = { a0.x, a0.y, a0.z, a0.w, a1.x, a1.y, a1.z, a1.w };
    float s = 0.f;
    #pragma unroll
    for (int i = 0; i < 8; i++) s += vv[i];
    float mean = warp_sum(s) * (1.f / 256.f);
    float s2 = 0.f;
    #pragma unroll
    for (int i = 0; i < 8; i++) { vv[i] -= mean; s2 += vv[i] * vv[i]; }
    float rstd = rsqrtf(warp_sum(s2) * (1.f / 256.f) + 1e-5f);
    float4 ga = *((const float4*)(gg) + lane * 2), gb = *((const float4*)(gg) + lane * 2 + 1);
    float4 ba = *((const float4*)(bb) + lane * 2), b2 = *((const float4*)(bb) + lane * 2 + 1);
    float gv[8] = { ga.x, ga.y, ga.z, ga.w, gb.x, gb.y, gb.z, gb.w };
    float bv[8] = { ba.x, ba.y, ba.z, ba.w, b2.x, b2.y, b2.z, b2.w };
    union { uint4 u; __half hx[8]; } pk;
    #pragma unroll
    for (int i = 0; i < 8; i++) pk.hx[i] = __float2half(vv[i] * rstd * gv[i] + bv[i]);
    *(uint4*)(g_acth + o) = pk.u;
}

// ---------------- launch --------------------------------------------------------
extern "C" void kernel_launch(void* const* d_in, const int* in_sizes, int n_in,
                              void* d_out, int out_size)
{
    (void)in_sizes; (void)n_in; (void)out_size;
    const float* x     = (const float*)d_in[0];
    const float* mask  = (const float*)d_in[1];
    const float* n1g   = (const float*)d_in[2];
    const float* n1b   = (const float*)d_in[3];
    const float* valw  = (const float*)d_in[4];
    const float* valb  = (const float*)d_in[5];
    const float* offw  = (const float*)d_in[6];
    const float* offbi = (const float*)d_in[7];
    const float* aww   = (const float*)d_in[8];
    const float* awbi  = (const float*)d_in[9];
    const float* outw  = (const float*)d_in[10];
    const float* outbi = (const float*)d_in[11];
    const float* ang   = (const float*)d_in[12];
    const float* anb   = (const float*)d_in[13];
    const float* projw = (const float*)d_in[14];
    const float* projb = (const float*)d_in[15];
    const float* n2g   = (const float*)d_in[16];
    const float* n2b   = (const float*)d_in[17];
    const float* fc1w  = (const float*)d_in[18];
    const float* fc1b  = (const float*)d_in[19];
    const float* fc2w  = (const float*)d_in[20];
    const float* fc2b  = (const float*)d_in[21];
    float* out = (float*)d_out;

    float *pOff, *pAw;
    __half *pActh, *pAct2h, *pHh, *pWh;
    cudaGetSymbolAddress((void**)&pOff,  g_offb);
    cudaGetSymbolAddress((void**)&pAw,   g_awb);
    cudaGetSymbolAddress((void**)&pActh, g_acth);
    cudaGetSymbolAddress((void**)&pAct2h,g_act2h);
    cudaGetSymbolAddress((void**)&pHh,   g_hh);
    cudaGetSymbolAddress((void**)&pWh,   g_wh);
    __half* pAttn = pHh + (size_t)TOT * CC;   // attn-out plane inside g_hh

    const int SMEM = 98304;   // 3 stages x 32KB
    cudaFuncSetAttribute(k_hgemm, cudaFuncAttributeMaxDynamicSharedMemorySize, SMEM);

    const int MT = TOT / 128;    // 392 row tiles
    const int LNG = TOT / 8;     // warp per token

    // 0. all weight converts in one launch
    k_wconv_all<<<2944, 256>>>(valw, offw, aww, outw, projw, fc1w, fc2w);
    // 1. LN1 + partition + diag -> acth (xw fp16), act2h (q fp16)
    k_ln1diag<<<LNG, 256>>>(x, mask, n1g, n1b);
    // 2+3 fused. bx<2: value = xw @ val_w -> g_hh value plane (fp16);
    //            bx==2: off/aw = q @ [off_w|aw_w] -> offb/awb (fp32)
    k_hgemm<<<dim3(3, MT), 256, SMEM>>>(pActh, pWh, pAct2h, pWh + 65536,
                                        valb, offbi, awbi,
                                        pOff, pAw, nullptr, pHh, 256, 256, 7);
    // 4. deformable sampling (softmax fused) -> act2h (D fp16)
    k_sample<<<NWIN * NHD, 256>>>();
    // 5. attn out = D @ out_w + b -> attn plane (fp16)
    k_hgemm<<<dim3(2, MT), 256, SMEM>>>(pAct2h, pWh + 98304, nullptr, nullptr,
                                        outbi, nullptr, nullptr,
                                        nullptr, nullptr, nullptr, pAttn, 256, 256, 6);
    // 6. acth = LN(xw + attn) with anorm
    k_addln<<<LNG, 256>>>(ang, anb);
    // 7. window-reverse + residual: out = x + (acth @ proj_w + b)
    k_hgemm<<<dim3(2, MT), 256, SMEM>>>(pActh, pWh + 163840, nullptr, nullptr,
                                        projb, nullptr, nullptr,
                                        out, nullptr, x, nullptr, 256, 256, 2);
    // 8. acth = LN2(out)
    k_ln2<<<LNG, 256>>>(out, n2g, n2b);
    // 9. H = gelu(acth @ fc1_w + b) -> g_hh (fp16 hidden)
    k_hgemm<<<dim3(8, MT), 256, SMEM>>>(pActh, pWh + 229376, nullptr, nullptr,
                                        fc1b, nullptr, nullptr,
                                        nullptr, nullptr, nullptr, pHh, 256, 1024, 4);
    // 10. out += H @ fc2_w + b
    k_hgemm<<<dim3(2, MT), 256, SMEM>>>(pHh, pWh + 491520, nullptr, nullptr,
                                        fc2b, nullptr, nullptr,
                                        out, nullptr, out, nullptr, 1024, 256, 3);
}

// round 16
// speedup vs baseline: 4.0227x; 1.1021x over previous
#include <cuda_runtime.h>
#include <cuda_fp16.h>
#include <math.h>
#include <stdint.h>

// Problem constants
#define CC    256
#define NTOK  98
#define NHD   8
#define HDIM  32
#define NWIN  512
#define TOT   (NWIN*NTOK)   // 50176
#define HHH   56
#define WWIDE 56

// ---------------- scratch (static device globals; no allocation) ----------------
__device__ __align__(16) float g_offb[(size_t)TOT*96];
__device__ __align__(16) float g_awb [(size_t)TOT*32];
__device__ __align__(16) __half g_acth [(size_t)TOT*CC];  // xw -> LN(x+attn) -> LN2
__device__ __align__(16) __half g_act2h[(size_t)TOT*CC];  // q -> sampled D
__device__ __align__(16) __half g_hh[(size_t)TOT*1024];   // [0,TC): value, [TC,2TC): attn; later fc1 hidden
__device__ __align__(16) __half g_wh[753664];             // all weights [N,K] fp16

// ---------------- PTX helpers (base-target features only) ----------------------
__device__ __forceinline__ uint32_t smem_u32(const void* p) {
    uint32_t a;
    asm("{ .reg .u64 t; cvta.to.shared.u64 t, %1; cvt.u32.u64 %0, t; }" : "=r"(a) : "l"(p));
    return a;
}
#define CPASYNC(sa, ga) asm volatile("cp.async.cg.shared.global [%0], [%1], 16;" :: "r"(sa), "l"(ga))
#define CPCOMMIT()      asm volatile("cp.async.commit_group;" ::: "memory")
#define CPWAIT1()       asm volatile("cp.async.wait_group 1;" ::: "memory")
#define CPWAIT0()       asm volatile("cp.async.wait_group 0;" ::: "memory")

__device__ __forceinline__ void ldsm_x4(uint32_t* r, uint32_t a) {
    asm volatile("ldmatrix.sync.aligned.m8n8.x4.shared.b16 {%0,%1,%2,%3}, [%4];"
                 : "=r"(r[0]), "=r"(r[1]), "=r"(r[2]), "=r"(r[3]) : "r"(a));
}
__device__ __forceinline__ void ldsm_x2(uint32_t* r, uint32_t a) {
    asm volatile("ldmatrix.sync.aligned.m8n8.x2.shared.b16 {%0,%1}, [%2];"
                 : "=r"(r[0]), "=r"(r[1]) : "r"(a));
}
__device__ __forceinline__ void mma16816(float* d, const uint32_t* a, const uint32_t* b) {
    asm volatile("mma.sync.aligned.m16n8k16.row.col.f32.f16.f16.f32 "
                 "{%0,%1,%2,%3}, {%4,%5,%6,%7}, {%8,%9}, {%0,%1,%2,%3};"
                 : "+f"(d[0]), "+f"(d[1]), "+f"(d[2]), "+f"(d[3])
                 : "r"(a[0]), "r"(a[1]), "r"(a[2]), "r"(a[3]), "r"(b[0]), "r"(b[1]));
}

// ---------------- small helpers ----------------
__device__ __forceinline__ float warp_sum(float v) {
    #pragma unroll
    for (int o = 16; o > 0; o >>= 1) v += __shfl_xor_sync(0xffffffffu, v, o);
    return v;
}
__device__ __forceinline__ float gelu_f(float x) {
    float x3 = x * x * x;
    return 0.5f * x * (1.f + tanhf(0.7978845608028654f * (x + 0.044715f * x3)));
}

// ---------------- stage 1: LN1 + window partition + diag (warp per token) -------
__global__ void k_ln1diag(const float* __restrict__ x, const float* __restrict__ mask,
                          const float* __restrict__ g1, const float* __restrict__ b1)
{
    int warp = threadIdx.x >> 5, lane = threadIdx.x & 31;
    int t = blockIdx.x * 8 + warp;
    int win = t / NTOK, n = t % NTOK;
    int dwn = win >> 6, hwn = (win >> 3) & 7, wwn = win & 7;
    int wd = n / 49, rm = n % 49, wh = rm / 7, wx = rm % 7;
    int d = dwn * 2 + wd, h = hwn * 7 + wh, w = wwn * 7 + wx;
    size_t g = ((size_t)d * HHH + h) * WWIDE + w;

    const float4* xp = (const float4*)(x + g * CC) + lane * 2;
    float4 v0 = xp[0], v1 = xp[1];
    float s = v0.x + v0.y + v0.z + v0.w + v1.x + v1.y + v1.z + v1.w;
    float mean = warp_sum(s) * (1.f / 256.f);
    float vv[8] = { v0.x - mean, v0.y - mean, v0.z - mean, v0.w - mean,
                    v1.x - mean, v1.y - mean, v1.z - mean, v1.w - mean };
    float s2 = 0.f;
    #pragma unroll
    for (int i = 0; i < 8; i++) s2 += vv[i] * vv[i];
    float rstd = rsqrtf(warp_sum(s2) * (1.f / 256.f) + 1e-5f);

    float diag = 0.f;
    if (lane == 0) {
        const float* mrow = mask + ((size_t)win * NTOK + n) * NTOK;
        float m = mrow[(wd * 7 + wh) * 7 + wx];
        float zs = 0.f, ys = 0.f, xs = 0.f;
        for (int z = 0; z <= wd; z++) zs += mrow[z * 49 + wh * 7 + wx];
        for (int y = 0; y <= wh; y++) ys += mrow[wd * 49 + y * 7 + wx];
        for (int xq = 0; xq <= wx; xq++) xs += mrow[wd * 49 + wh * 7 + xq];
        const float INV_PI = 0.3183098861837907f;
        const float PI_F   = 3.14159265358979323846f;
        diag = m * (sinf(xs * m * INV_PI) + sinf(PI_F * ys * m * INV_PI) + zs * m * INV_PI);
    }
    diag = __shfl_sync(0xffffffffu, diag, 0);

    float4 ga = *((const float4*)(g1) + lane * 2), gb = *((const float4*)(g1) + lane * 2 + 1);
    float4 ba = *((const float4*)(b1) + lane * 2), bb = *((const float4*)(b1) + lane * 2 + 1);
    float gg[8] = { ga.x, ga.y, ga.z, ga.w, gb.x, gb.y, gb.z, gb.w };
    float bbv[8] = { ba.x, ba.y, ba.z, ba.w, bb.x, bb.y, bb.z, bb.w };

    size_t o = (size_t)t * CC + lane * 8;
    union { uint4 u; __half hx[8]; } p1, p2;
    #pragma unroll
    for (int i = 0; i < 8; i++) {
        float xn = vv[i] * rstd * gg[i] + bbv[i];
        p1.hx[i] = __float2half(xn);
        p2.hx[i] = __float2half(xn + diag);
    }
    *(uint4*)(g_acth + o)  = p1.u;
    *(uint4*)(g_act2h + o) = p2.u;
}

// ---------------- all-weights convert (+transpose to [N,K], fp16) ---------------
__global__ void k_wconv_all(const float* __restrict__ w0, const float* __restrict__ w1,
                            const float* __restrict__ w2, const float* __restrict__ w3,
                            const float* __restrict__ w4, const float* __restrict__ w5,
                            const float* __restrict__ w6)
{
    int gid = blockIdx.x * 256 + threadIdx.x;
    const float* src; int base, Kd, Nd, e;
    if      (gid < 65536)  { src = w0; base = 0;      Kd = 256;  Nd = 256;  e = gid; }
    else if (gid < 90112)  { src = w1; base = 65536;  Kd = 256;  Nd = 96;   e = gid - 65536; }
    else if (gid < 98304)  { src = w2; base = 90112;  Kd = 256;  Nd = 32;   e = gid - 90112; }
    else if (gid < 163840) { src = w3; base = 98304;  Kd = 256;  Nd = 256;  e = gid - 98304; }
    else if (gid < 229376) { src = w4; base = 163840; Kd = 256;  Nd = 256;  e = gid - 163840; }
    else if (gid < 491520) { src = w5; base = 229376; Kd = 256;  Nd = 1024; e = gid - 229376; }
    else                   { src = w6; base = 491520; Kd = 1024; Nd = 256;  e = gid - 491520; }
    int k = e / Nd, n = e % Nd;
    g_wh[(size_t)base + (size_t)n * Kd + k] = __float2half(src[(size_t)k * Nd + n]);
}

// ---------------- fp16 mma.sync GEMM, 3-stage cp.async pipeline ------------------
// modes: 2 winrev+residual; 3 residual add; 4 gelu->fp16; 5 off/aw split;
//        6 plain fp16 store; 7 fused dispatch (bx<2: mode6 A/B, bx==2: mode5 A2/B2)
__global__ void __launch_bounds__(256, 2)
k_hgemm(const __half* __restrict__ A, const __half* __restrict__ B,
        const __half* __restrict__ A2, const __half* __restrict__ B2,
        const float* __restrict__ bias, const float* __restrict__ bias2,
        const float* __restrict__ bias3,
        float* __restrict__ out, float* __restrict__ out2,
        const float* __restrict__ aux, __half* __restrict__ outh,
        int K, int ldo, int mode)
{
    extern __shared__ char smem[];
    constexpr int STG = 32768;   // per-stage: A 16K | B 16K
    int tid = threadIdx.x, wid = tid >> 5, lid = tid & 31;
    int row0 = blockIdx.y * 128;
    int n0 = blockIdx.x * 128;
    int nk = K >> 6;

    if (mode == 7) {
        if (blockIdx.x == 2) { A = A2; B = B2; bias = bias2; bias2 = bias3; n0 = 0; mode = 5; }
        else                 { mode = 6; }
    }

    auto load_stage = [&](int ci, int s) {
        size_t ak = (size_t)row0 * K + ci * 64;
        size_t bk = (size_t)n0 * K + ci * 64;
        char* base = smem + s * STG;
        #pragma unroll
        for (int j = 0; j < 8; j++) {
            int idx = tid + j * 256;
            int seg = idx >> 10;            // 0:A 1:B
            int r = (idx >> 3) & 127;
            int c = idx & 7;
            uint32_t so = (uint32_t)(r * 128 + c * 16);
            so ^= (so >> 3) & 0x70;          // SW128 swizzle
            const __half* gp = seg ? (B + bk + (size_t)r * K + c * 8)
                                   : (A + ak + (size_t)r * K + c * 8);
            CPASYNC(smem_u32(base + seg * 16384 + so), gp);
        }
        CPCOMMIT();
    };

    float acc[4][4][4];
    #pragma unroll
    for (int a = 0; a < 4; a++)
        #pragma unroll
        for (int b = 0; b < 4; b++)
            #pragma unroll
            for (int c = 0; c < 4; c++) acc[a][b][c] = 0.f;

    int warp_m = wid >> 2, warp_n = wid & 3;     // 2 x 4 warp grid, warp tile 64x32
    int lrow_a = lid & 15, lcol_a = (lid >> 4) * 16;
    int l15 = lid & 15;
    int lrow_b = l15 & 7, lcol_b = (l15 >> 3) * 16;

    load_stage(0, 0);
    if (nk > 1) load_stage(1, 1);
    int sc = 0;                    // stage index of chunk i
    for (int i = 0; i < nk; i++) {
        if (i < nk - 1) CPWAIT1(); else CPWAIT0();
        __syncthreads();
        if (i + 2 < nk) {
            int sl = sc + 2; if (sl >= 3) sl -= 3;
            load_stage(i + 2, sl);
        }
        char* sb = smem + sc * STG;
        uint32_t aS = smem_u32(sb), bS = aS + 16384;
        #pragma unroll
        for (int ks = 0; ks < 4; ks++) {
            int kb = ks * 32;                    // byte offset of 16-elem k group
            uint32_t af[4][4], bf[4][2];
            #pragma unroll
            for (int mt = 0; mt < 4; mt++) {
                uint32_t o = (uint32_t)((warp_m * 64 + mt * 16 + lrow_a) * 128 + kb + lcol_a);
                o ^= (o >> 3) & 0x70;
                ldsm_x4(af[mt], aS + o);
            }
            #pragma unroll
            for (int nt = 0; nt < 4; nt++) {
                uint32_t o = (uint32_t)((warp_n * 32 + nt * 8 + lrow_b) * 128 + kb + lcol_b);
                o ^= (o >> 3) & 0x70;
                ldsm_x2(bf[nt], bS + o);
            }
            #pragma unroll
            for (int mt = 0; mt < 4; mt++)
                #pragma unroll
                for (int nt = 0; nt < 4; nt++)
                    mma16816(acc[mt][nt], af[mt], bf[nt]);
        }
        if (++sc == 3) sc = 0;
        // note: no trailing __syncthreads — top barrier orders slot reuse (3 stages)
    }

    // ---- epilogue ----
    int lr = lid >> 2, lc = (lid & 3) * 2;
    #pragma unroll
    for (int mt = 0; mt < 4; mt++) {
        int rbase = row0 + warp_m * 64 + mt * 16 + lr;
        #pragma unroll
        for (int half = 0; half < 2; half++) {
            int r = rbase + half * 8;
            size_t g2 = 0;
            if (mode == 2) {
                int win = r / NTOK, n_ = r % NTOK;
                int dwn = win >> 6, hwn = (win >> 3) & 7, wwn = win & 7;
                int wd = n_ / 49, rm = n_ % 49, wh = rm / 7, wx = rm % 7;
                g2 = ((size_t)(dwn * 2 + wd) * HHH + (hwn * 7 + wh)) * WWIDE + (wwn * 7 + wx);
            }
            #pragma unroll
            for (int nt = 0; nt < 4; nt++) {
                int col = n0 + warp_n * 32 + nt * 8 + lc;
                float v0 = acc[mt][nt][half * 2 + 0];
                float v1 = acc[mt][nt][half * 2 + 1];
                if (mode == 5) {
                    if (col < 96) {
                        v0 += __ldg(bias + col);  v1 += __ldg(bias + col + 1);
                        *(float2*)(out + (size_t)r * 96 + col) = make_float2(v0, v1);
                    } else {
                        v0 += __ldg(bias2 + col - 96);  v1 += __ldg(bias2 + col - 95);
                        *(float2*)(out2 + (size_t)r * 32 + (col - 96)) = make_float2(v0, v1);
                    }
                } else if (mode == 4 || mode == 6) {
                    float h0 = v0 + __ldg(bias + col);
                    float h1 = v1 + __ldg(bias + col + 1);
                    if (mode == 4) { h0 = gelu_f(h0); h1 = gelu_f(h1); }
                    __half2 hp; hp.x = __float2half(h0); hp.y = __float2half(h1);
                    *(__half2*)(outh + (size_t)r * ldo + col) = hp;
                } else {
                    v0 += __ldg(bias + col);  v1 += __ldg(bias + col + 1);
                    if (mode == 3) {
                        float2 a = *(const float2*)(aux + (size_t)r * ldo + col);
                        *(float2*)(out + (size_t)r * ldo + col) = make_float2(v0 + a.x, v1 + a.y);
                    } else { // mode 2
                        float2 a = *(const float2*)(aux + g2 * 256 + col);
                        *(float2*)(out + g2 * 256 + col) = make_float2(v0 + a.x, v1 + a.y);
                    }
                }
            }
        }
    }
}

// ---------------- deformable sampling + fused softmax -> D fp16 -----------------
// Note: px = (rx + ox/W)*W - 0.5 with rx=(xq+0.5)/W collapses to px = xq + ox.
__global__ void k_sample()
{
    __shared__ float sval[NTOK * HDIM];
    int win  = blockIdx.x >> 3;
    int head = blockIdx.x & 7;

    // vectorized fp16 load of the value plane: 98 rows x 32 ch (4 x uint4 per row)
    const __half* vplane = g_hh + (size_t)win * NTOK * CC + head * HDIM;
    for (int i = threadIdx.x; i < NTOK * 4; i += 256) {
        int s = i >> 2, seg = i & 3;
        union { uint4 u; __half h[8]; } pk;
        pk.u = *(const uint4*)(vplane + (size_t)s * CC + seg * 8);
        #pragma unroll
        for (int k = 0; k < 8; k++) sval[s * HDIM + seg * 8 + k] = __half2float(pk.h[k]);
    }
    __syncthreads();

    int warp = threadIdx.x >> 5, lane = threadIdx.x & 31;
    for (int nn = warp; nn < NTOK; nn += 8) {
        int t = win * NTOK + nn;
        int z = nn / 49, rm = nn % 49, y = rm / 7, xq = rm % 7;
        const float4* offp = (const float4*)(g_offb + (size_t)t * 96 + head * 12);
        float4 o0 = offp[0], o1 = offp[1], o2 = offp[2];
        float offs[12] = { o0.x, o0.y, o0.z, o0.w, o1.x, o1.y, o1.z, o1.w,
                           o2.x, o2.y, o2.z, o2.w };
        float4 lg = *(const float4*)(g_awb + (size_t)t * 32 + head * 4);
        float mx = fmaxf(fmaxf(lg.x, lg.y), fmaxf(lg.z, lg.w));
        float e0 = __expf(lg.x - mx), e1 = __expf(lg.y - mx);
        float e2 = __expf(lg.z - mx), e3 = __expf(lg.w - mx);
        float inv = 1.f / (e0 + e1 + e2 + e3);
        float awv[4] = { e0 * inv, e1 * inv, e2 * inv, e3 * inv };

        float tot = 0.f;
        #pragma unroll
        for (int p = 0; p < 4; p++) {
            float px = xq + offs[p * 3 + 0];
            float py = y  + offs[p * 3 + 1];
            float pz = z  + offs[p * 3 + 2];
            float fx0 = floorf(px), fy0 = floorf(py), fz0 = floorf(pz);
            float fx = px - fx0, fy = py - fy0, fz = pz - fz0;
            int ix = (int)fx0, iy = (int)fy0, iz = (int)fz0;
            // factored weights with validity folded in; aw folded into wz
            float wx0 = (ix >= 0 && ix < 7)       ? 1.f - fx : 0.f;
            float wx1 = (ix >= -1 && ix < 6)      ? fx       : 0.f;
            float wy0 = (iy >= 0 && iy < 7)       ? 1.f - fy : 0.f;
            float wy1 = (iy >= -1 && iy < 6)      ? fy       : 0.f;
            float wz0 = (iz == 0 || iz == 1)      ? awv[p] * (1.f - fz) : 0.f;
            float wz1 = (iz == -1 || iz == 0)     ? awv[p] * fz         : 0.f;
            int cx0 = min(max(ix, 0), 6),     cx1 = min(max(ix + 1, 0), 6);
            int cy0 = min(max(iy, 0), 6),     cy1 = min(max(iy + 1, 0), 6);
            int cz0 = min(max(iz, 0), 1),     cz1 = min(max(iz + 1, 0), 1);
            // 4 (z,y) combos
            float w00 = wz0 * wy0; int b00 = ((cz0 * 7 + cy0) * 7) * HDIM + lane;
            float w01 = wz0 * wy1; int b01 = ((cz0 * 7 + cy1) * 7) * HDIM + lane;
            float w10 = wz1 * wy0; int b10 = ((cz1 * 7 + cy0) * 7) * HDIM + lane;
            float w11 = wz1 * wy1; int b11 = ((cz1 * 7 + cy1) * 7) * HDIM + lane;
            int ox0 = cx0 * HDIM, ox1 = cx1 * HDIM;
            float s00 = wx0 * sval[b00 + ox0] + wx1 * sval[b00 + ox1];
            float s01 = wx0 * sval[b01 + ox0] + wx1 * sval[b01 + ox1];
            float s10 = wx0 * sval[b10 + ox0] + wx1 * sval[b10 + ox1];
            float s11 = wx0 * sval[b11 + ox0] + wx1 * sval[b11 + ox1];
            tot += w00 * s00 + w01 * s01 + w10 * s10 + w11 * s11;
        }
        g_act2h[(size_t)t * CC + head * HDIM + lane] = __float2half(tot);
    }
}

// ---------------- residual(xw fp16 + attn fp16) + LN (anorm) -> acth ------------
__global__ void k_addln(const float* __restrict__ gg, const float* __restrict__ bb)
{
    int warp = threadIdx.x >> 5, lane = threadIdx.x & 31;
    int t = blockIdx.x * 8 + warp;
    size_t o = (size_t)t * CC + lane * 8;
    union { uint4 u; __half h[8]; } xa, ea;
    xa.u = *(const uint4*)(g_acth + o);
    ea.u = *(const uint4*)(g_hh + (size_t)TOT * CC + o);
    float vv[8];
    #pragma unroll
    for (int i = 0; i < 8; i++) vv[i] = __half2float(xa.h[i]) + __half2float(ea.h[i]);
    float s = 0.f;
    #pragma unroll
    for (int i = 0; i < 8; i++) s += vv[i];
    float mean = warp_sum(s) * (1.f / 256.f);
    float s2 = 0.f;
    #pragma unroll
    for (int i = 0; i < 8; i++) { vv[i] -= mean; s2 += vv[i] * vv[i]; }
    float rstd = rsqrtf(warp_sum(s2) * (1.f / 256.f) + 1e-5f);
    float4 ga = *((const float4*)(gg) + lane * 2), gb = *((const float4*)(gg) + lane * 2 + 1);
    float4 ba = *((const float4*)(bb) + lane * 2), b2 = *((const float4*)(bb) + lane * 2 + 1);
    float gv[8] = { ga.x, ga.y, ga.z, ga.w, gb.x, gb.y, gb.z, gb.w };
    float bv[8] = { ba.x, ba.y, ba.z, ba.w, b2.x, b2.y, b2.z, b2.w };
    union { uint4 u; __half hx[8]; } pk;
    #pragma unroll
    for (int i = 0; i < 8; i++) pk.hx[i] = __float2half(vv[i] * rstd * gv[i] + bv[i]);
    *(uint4*)(g_acth + o) = pk.u;
}

// ---------------- LN2, warp per token -> acth fp16 ------------------------------
__global__ void k_ln2(const float* __restrict__ xin,
                      const float* __restrict__ gg, const float* __restrict__ bb)
{
    int warp = threadIdx.x >> 5, lane = threadIdx.x & 31;
    int t = blockIdx.x * 8 + warp;
    size_t o = (size_t)t * CC + lane * 8;
    float4 a0 = *(const float4*)(xin + o), a1 = *(const float4*)(xin + o + 4);
    float vv[8] = { a0.x, a0.y, a0.z, a0.w, a1.x, a1.y, a1.z, a1.w };
    float s = 0.f;
    #pragma unroll
    for (int i = 0; i < 8; i++) s += vv[i];
    float mean = warp_sum(s) * (1.f / 256.f);
    float s2 = 0.f;
    #pragma unroll
    for (int i = 0; i < 8; i++) { vv[i] -= mean; s2 += vv[i] * vv[i]; }
    float rstd = rsqrtf(warp_sum(s2) * (1.f / 256.f) + 1e-5f);
    float4 ga = *((const float4*)(gg) + lane * 2), gb = *((const float4*)(gg) + lane * 2 + 1);
    float4 ba = *((const float4*)(bb) + lane * 2), b2 = *((const float4*)(bb) + lane * 2 + 1);
    float gv[8] = { ga.x, ga.y, ga.z, ga.w, gb.x, gb.y, gb.z, gb.w };
    float bv[8] = { ba.x, ba.y, ba.z, ba.w, b2.x, b2.y, b2.z, b2.w };
    union { uint4 u; __half hx[8]; } pk;
    #pragma unroll
    for (int i = 0; i < 8; i++) pk.hx[i] = __float2half(vv[i] * rstd * gv[i] + bv[i]);
    *(uint4*)(g_acth + o) = pk.u;
}

// ---------------- launch --------------------------------------------------------
extern "C" void kernel_launch(void* const* d_in, const int* in_sizes, int n_in,
                              void* d_out, int out_size)
{
    (void)in_sizes; (void)n_in; (void)out_size;
    const float* x     = (const float*)d_in[0];
    const float* mask  = (const float*)d_in[1];
    const float* n1g   = (const float*)d_in[2];
    const float* n1b   = (const float*)d_in[3];
    const float* valw  = (const float*)d_in[4];
    const float* valb  = (const float*)d_in[5];
    const float* offw  = (const float*)d_in[6];
    const float* offbi = (const float*)d_in[7];
    const float* aww   = (const float*)d_in[8];
    const float* awbi  = (const float*)d_in[9];
    const float* outw  = (const float*)d_in[10];
    const float* outbi = (const float*)d_in[11];
    const float* ang   = (const float*)d_in[12];
    const float* anb   = (const float*)d_in[13];
    const float* projw = (const float*)d_in[14];
    const float* projb = (const float*)d_in[15];
    const float* n2g   = (const float*)d_in[16];
    const float* n2b   = (const float*)d_in[17];
    const float* fc1w  = (const float*)d_in[18];
    const float* fc1b  = (const float*)d_in[19];
    const float* fc2w  = (const float*)d_in[20];
    const float* fc2b  = (const float*)d_in[21];
    float* out = (float*)d_out;

    float *pOff, *pAw;
    __half *pActh, *pAct2h, *pHh, *pWh;
    cudaGetSymbolAddress((void**)&pOff,  g_offb);
    cudaGetSymbolAddress((void**)&pAw,   g_awb);
    cudaGetSymbolAddress((void**)&pActh, g_acth);
    cudaGetSymbolAddress((void**)&pAct2h,g_act2h);
    cudaGetSymbolAddress((void**)&pHh,   g_hh);
    cudaGetSymbolAddress((void**)&pWh,   g_wh);
    __half* pAttn = pHh + (size_t)TOT * CC;   // attn-out plane inside g_hh

    const int SMEM = 98304;   // 3 stages x 32KB
    cudaFuncSetAttribute(k_hgemm, cudaFuncAttributeMaxDynamicSharedMemorySize, SMEM);

    const int MT = TOT / 128;    // 392 row tiles
    const int LNG = TOT / 8;     // warp per token

    // 0. all weight converts in one launch
    k_wconv_all<<<2944, 256>>>(valw, offw, aww, outw, projw, fc1w, fc2w);
    // 1. LN1 + partition + diag -> acth (xw fp16), act2h (q fp16)
    k_ln1diag<<<LNG, 256>>>(x, mask, n1g, n1b);
    // 2+3 fused. bx<2: value = xw @ val_w -> g_hh value plane (fp16);
    //            bx==2: off/aw = q @ [off_w|aw_w] -> offb/awb (fp32)
    k_hgemm<<<dim3(3, MT), 256, SMEM>>>(pActh, pWh, pAct2h, pWh + 65536,
                                        valb, offbi, awbi,
                                        pOff, pAw, nullptr, pHh, 256, 256, 7);
    // 4. deformable sampling (softmax fused) -> act2h (D fp16)
    k_sample<<<NWIN * NHD, 256>>>();
    // 5. attn out = D @ out_w + b -> attn plane (fp16)
    k_hgemm<<<dim3(2, MT), 256, SMEM>>>(pAct2h, pWh + 98304, nullptr, nullptr,
                                        outbi, nullptr, nullptr,
                                        nullptr, nullptr, nullptr, pAttn, 256, 256, 6);
    // 6. acth = LN(xw + attn) with anorm
    k_addln<<<LNG, 256>>>(ang, anb);
    // 7. window-reverse + residual: out = x + (acth @ proj_w + b)
    k_hgemm<<<dim3(2, MT), 256, SMEM>>>(pActh, pWh + 163840, nullptr, nullptr,
                                        projb, nullptr, nullptr,
                                        out, nullptr, x, nullptr, 256, 256, 2);
    // 8. acth = LN2(out)
    k_ln2<<<LNG, 256>>>(out, n2g, n2b);
    // 9. H = gelu(acth @ fc1_w + b) -> g_hh (fp16 hidden)
    k_hgemm<<<dim3(8, MT), 256, SMEM>>>(pActh, pWh + 229376, nullptr, nullptr,
                                        fc1b, nullptr, nullptr,
                                        nullptr, nullptr, nullptr, pHh, 256, 1024, 4);
    // 10. out += H @ fc2_w + b
    k_hgemm<<<dim3(2, MT), 256, SMEM>>>(pHh, pWh + 491520, nullptr, nullptr,
                                        fc2b, nullptr, nullptr,
                                        out, nullptr, out, nullptr, 1024, 256, 3);
}

// round 17
// speedup vs baseline: 4.3942x; 1.0923x over previous
#include <cuda_runtime.h>
#include <cuda_fp16.h>
#include <math.h>
#include <stdint.h>

// Problem constants
#define CC    256
#define NTOK  98
#define NHD   8
#define HDIM  32
#define NWIN  512
#define TOT   (NWIN*NTOK)   // 50176
#define HHH   56
#define WWIDE 56

// ---------------- scratch (static device globals; no allocation) ----------------
__device__ __align__(16) float g_offb[(size_t)TOT*96];
__device__ __align__(16) float g_awb [(size_t)TOT*32];
__device__ __align__(16) __half g_acth [(size_t)TOT*CC];  // xw -> LN(x+attn) -> LN2
__device__ __align__(16) __half g_act2h[(size_t)TOT*CC];  // q -> sampled D
__device__ __align__(16) __half g_hh[(size_t)TOT*1024];   // [0,TC): value, [TC,2TC): attn; later fc1 hidden
__device__ __align__(16) __half g_wh[753664];             // all weights [N,K] fp16

// ---------------- PTX helpers (base-target features only) ----------------------
__device__ __forceinline__ uint32_t smem_u32(const void* p) {
    uint32_t a;
    asm("{ .reg .u64 t; cvta.to.shared.u64 t, %1; cvt.u32.u64 %0, t; }" : "=r"(a) : "l"(p));
    return a;
}
#define CPASYNC(sa, ga) asm volatile("cp.async.cg.shared.global [%0], [%1], 16;" :: "r"(sa), "l"(ga))
#define CPCOMMIT()      asm volatile("cp.async.commit_group;" ::: "memory")
#define CPWAIT1()       asm volatile("cp.async.wait_group 1;" ::: "memory")
#define CPWAIT0()       asm volatile("cp.async.wait_group 0;" ::: "memory")

__device__ __forceinline__ void ldsm_x4(uint32_t* r, uint32_t a) {
    asm volatile("ldmatrix.sync.aligned.m8n8.x4.shared.b16 {%0,%1,%2,%3}, [%4];"
                 : "=r"(r[0]), "=r"(r[1]), "=r"(r[2]), "=r"(r[3]) : "r"(a));
}
__device__ __forceinline__ void ldsm_x2(uint32_t* r, uint32_t a) {
    asm volatile("ldmatrix.sync.aligned.m8n8.x2.shared.b16 {%0,%1}, [%2];"
                 : "=r"(r[0]), "=r"(r[1]) : "r"(a));
}
__device__ __forceinline__ void mma16816(float* d, const uint32_t* a, const uint32_t* b) {
    asm volatile("mma.sync.aligned.m16n8k16.row.col.f32.f16.f16.f32 "
                 "{%0,%1,%2,%3}, {%4,%5,%6,%7}, {%8,%9}, {%0,%1,%2,%3};"
                 : "+f"(d[0]), "+f"(d[1]), "+f"(d[2]), "+f"(d[3])
                 : "r"(a[0]), "r"(a[1]), "r"(a[2]), "r"(a[3]), "r"(b[0]), "r"(b[1]));
}

// ---------------- small helpers ----------------
__device__ __forceinline__ float warp_sum(float v) {
    #pragma unroll
    for (int o = 16; o > 0; o >>= 1) v += __shfl_xor_sync(0xffffffffu, v, o);
    return v;
}
__device__ __forceinline__ float gelu_f(float x) {
    float x3 = x * x * x;
    return 0.5f * x * (1.f + tanhf(0.7978845608028654f * (x + 0.044715f * x3)));
}

// ---------------- stage 1: LN1 + window partition + diag (warp per token) -------
__global__ void k_ln1diag(const float* __restrict__ x, const float* __restrict__ mask,
                          const float* __restrict__ g1, const float* __restrict__ b1)
{
    int warp = threadIdx.x >> 5, lane = threadIdx.x & 31;
    int t = blockIdx.x * 8 + warp;
    int win = t / NTOK, n = t % NTOK;
    int dwn = win >> 6, hwn = (win >> 3) & 7, wwn = win & 7;
    int wd = n / 49, rm = n % 49, wh = rm / 7, wx = rm % 7;
    int d = dwn * 2 + wd, h = hwn * 7 + wh, w = wwn * 7 + wx;
    size_t g = ((size_t)d * HHH + h) * WWIDE + w;

    const float4* xp = (const float4*)(x + g * CC) + lane * 2;
    float4 v0 = xp[0], v1 = xp[1];
    float s = v0.x + v0.y + v0.z + v0.w + v1.x + v1.y + v1.z + v1.w;
    float mean = warp_sum(s) * (1.f / 256.f);
    float vv[8] = { v0.x - mean, v0.y - mean, v0.z - mean, v0.w - mean,
                    v1.x - mean, v1.y - mean, v1.z - mean, v1.w - mean };
    float s2 = 0.f;
    #pragma unroll
    for (int i = 0; i < 8; i++) s2 += vv[i] * vv[i];
    float rstd = rsqrtf(warp_sum(s2) * (1.f / 256.f) + 1e-5f);

    float diag = 0.f;
    if (lane == 0) {
        const float* mrow = mask + ((size_t)win * NTOK + n) * NTOK;
        float m = mrow[(wd * 7 + wh) * 7 + wx];
        float zs = 0.f, ys = 0.f, xs = 0.f;
        for (int z = 0; z <= wd; z++) zs += mrow[z * 49 + wh * 7 + wx];
        for (int y = 0; y <= wh; y++) ys += mrow[wd * 49 + y * 7 + wx];
        for (int xq = 0; xq <= wx; xq++) xs += mrow[wd * 49 + wh * 7 + xq];
        const float INV_PI = 0.3183098861837907f;
        const float PI_F   = 3.14159265358979323846f;
        diag = m * (sinf(xs * m * INV_PI) + sinf(PI_F * ys * m * INV_PI) + zs * m * INV_PI);
    }
    diag = __shfl_sync(0xffffffffu, diag, 0);

    float4 ga = *((const float4*)(g1) + lane * 2), gb = *((const float4*)(g1) + lane * 2 + 1);
    float4 ba = *((const float4*)(b1) + lane * 2), bb = *((const float4*)(b1) + lane * 2 + 1);
    float gg[8] = { ga.x, ga.y, ga.z, ga.w, gb.x, gb.y, gb.z, gb.w };
    float bbv[8] = { ba.x, ba.y, ba.z, ba.w, bb.x, bb.y, bb.z, bb.w };

    size_t o = (size_t)t * CC + lane * 8;
    union { uint4 u; __half hx[8]; } p1, p2;
    #pragma unroll
    for (int i = 0; i < 8; i++) {
        float xn = vv[i] * rstd * gg[i] + bbv[i];
        p1.hx[i] = __float2half(xn);
        p2.hx[i] = __float2half(xn + diag);
    }
    *(uint4*)(g_acth + o)  = p1.u;
    *(uint4*)(g_act2h + o) = p2.u;
}

// ---------------- all-weights convert (+transpose to [N,K], fp16) ---------------
__global__ void k_wconv_all(const float* __restrict__ w0, const float* __restrict__ w1,
                            const float* __restrict__ w2, const float* __restrict__ w3,
                            const float* __restrict__ w4, const float* __restrict__ w5,
                            const float* __restrict__ w6)
{
    int gid = blockIdx.x * 256 + threadIdx.x;
    const float* src; int base, Kd, Nd, e;
    if      (gid < 65536)  { src = w0; base = 0;      Kd = 256;  Nd = 256;  e = gid; }
    else if (gid < 90112)  { src = w1; base = 65536;  Kd = 256;  Nd = 96;   e = gid - 65536; }
    else if (gid < 98304)  { src = w2; base = 90112;  Kd = 256;  Nd = 32;   e = gid - 90112; }
    else if (gid < 163840) { src = w3; base = 98304;  Kd = 256;  Nd = 256;  e = gid - 98304; }
    else if (gid < 229376) { src = w4; base = 163840; Kd = 256;  Nd = 256;  e = gid - 163840; }
    else if (gid < 491520) { src = w5; base = 229376; Kd = 256;  Nd = 1024; e = gid - 229376; }
    else                   { src = w6; base = 491520; Kd = 1024; Nd = 256;  e = gid - 491520; }
    int k = e / Nd, n = e % Nd;
    g_wh[(size_t)base + (size_t)n * Kd + k] = __float2half(src[(size_t)k * Nd + n]);
}

// ---------------- fp16 mma.sync GEMM, 3-stage cp.async pipeline ------------------
// modes: 2 winrev+residual; 3 residual add; 4 gelu->fp16; 5 off/aw split;
//        6 plain fp16 store; 7 fused dispatch (bx<2: mode6 A/B, bx==2: mode5 A2/B2)
__global__ void __launch_bounds__(256, 2)
k_hgemm(const __half* __restrict__ A, const __half* __restrict__ B,
        const __half* __restrict__ A2, const __half* __restrict__ B2,
        const float* __restrict__ bias, const float* __restrict__ bias2,
        const float* __restrict__ bias3,
        float* __restrict__ out, float* __restrict__ out2,
        const float* __restrict__ aux, __half* __restrict__ outh,
        int K, int ldo, int mode)
{
    extern __shared__ char smem[];
    constexpr int STG = 32768;   // per-stage: A 16K | B 16K
    int tid = threadIdx.x, wid = tid >> 5, lid = tid & 31;
    int row0 = blockIdx.y * 128;
    int n0 = blockIdx.x * 128;
    int nk = K >> 6;

    if (mode == 7) {
        if (blockIdx.x == 2) { A = A2; B = B2; bias = bias2; bias2 = bias3; n0 = 0; mode = 5; }
        else                 { mode = 6; }
    }

    auto load_stage = [&](int ci, int s) {
        size_t ak = (size_t)row0 * K + ci * 64;
        size_t bk = (size_t)n0 * K + ci * 64;
        char* base = smem + s * STG;
        #pragma unroll
        for (int j = 0; j < 8; j++) {
            int idx = tid + j * 256;
            int seg = idx >> 10;            // 0:A 1:B
            int r = (idx >> 3) & 127;
            int c = idx & 7;
            uint32_t so = (uint32_t)(r * 128 + c * 16);
            so ^= (so >> 3) & 0x70;          // SW128 swizzle
            const __half* gp = seg ? (B + bk + (size_t)r * K + c * 8)
                                   : (A + ak + (size_t)r * K + c * 8);
            CPASYNC(smem_u32(base + seg * 16384 + so), gp);
        }
        CPCOMMIT();
    };

    float acc[4][4][4];
    #pragma unroll
    for (int a = 0; a < 4; a++)
        #pragma unroll
        for (int b = 0; b < 4; b++)
            #pragma unroll
            for (int c = 0; c < 4; c++) acc[a][b][c] = 0.f;

    int warp_m = wid >> 2, warp_n = wid & 3;     // 2 x 4 warp grid, warp tile 64x32
    int lrow_a = lid & 15, lcol_a = (lid >> 4) * 16;
    int l15 = lid & 15;
    int lrow_b = l15 & 7, lcol_b = (l15 >> 3) * 16;

    load_stage(0, 0);
    if (nk > 1) load_stage(1, 1);
    int sc = 0;                    // stage index of chunk i
    for (int i = 0; i < nk; i++) {
        if (i < nk - 1) CPWAIT1(); else CPWAIT0();
        __syncthreads();
        if (i + 2 < nk) {
            int sl = sc + 2; if (sl >= 3) sl -= 3;
            load_stage(i + 2, sl);
        }
        char* sb = smem + sc * STG;
        uint32_t aS = smem_u32(sb), bS = aS + 16384;
        #pragma unroll
        for (int ks = 0; ks < 4; ks++) {
            int kb = ks * 32;                    // byte offset of 16-elem k group
            uint32_t af[4][4], bf[4][2];
            #pragma unroll
            for (int mt = 0; mt < 4; mt++) {
                uint32_t o = (uint32_t)((warp_m * 64 + mt * 16 + lrow_a) * 128 + kb + lcol_a);
                o ^= (o >> 3) & 0x70;
                ldsm_x4(af[mt], aS + o);
            }
            #pragma unroll
            for (int nt = 0; nt < 4; nt++) {
                uint32_t o = (uint32_t)((warp_n * 32 + nt * 8 + lrow_b) * 128 + kb + lcol_b);
                o ^= (o >> 3) & 0x70;
                ldsm_x2(bf[nt], bS + o);
            }
            #pragma unroll
            for (int mt = 0; mt < 4; mt++)
                #pragma unroll
                for (int nt = 0; nt < 4; nt++)
                    mma16816(acc[mt][nt], af[mt], bf[nt]);
        }
        if (++sc == 3) sc = 0;
        // note: no trailing __syncthreads — top barrier orders slot reuse (3 stages)
    }

    // ---- epilogue ----
    int lr = lid >> 2, lc = (lid & 3) * 2;
    #pragma unroll
    for (int mt = 0; mt < 4; mt++) {
        int rbase = row0 + warp_m * 64 + mt * 16 + lr;
        #pragma unroll
        for (int half = 0; half < 2; half++) {
            int r = rbase + half * 8;
            size_t g2 = 0;
            if (mode == 2) {
                int win = r / NTOK, n_ = r % NTOK;
                int dwn = win >> 6, hwn = (win >> 3) & 7, wwn = win & 7;
                int wd = n_ / 49, rm = n_ % 49, wh = rm / 7, wx = rm % 7;
                g2 = ((size_t)(dwn * 2 + wd) * HHH + (hwn * 7 + wh)) * WWIDE + (wwn * 7 + wx);
            }
            #pragma unroll
            for (int nt = 0; nt < 4; nt++) {
                int col = n0 + warp_n * 32 + nt * 8 + lc;
                float v0 = acc[mt][nt][half * 2 + 0];
                float v1 = acc[mt][nt][half * 2 + 1];
                if (mode == 5) {
                    if (col < 96) {
                        v0 += __ldg(bias + col);  v1 += __ldg(bias + col + 1);
                        *(float2*)(out + (size_t)r * 96 + col) = make_float2(v0, v1);
                    } else {
                        v0 += __ldg(bias2 + col - 96);  v1 += __ldg(bias2 + col - 95);
                        *(float2*)(out2 + (size_t)r * 32 + (col - 96)) = make_float2(v0, v1);
                    }
                } else if (mode == 4 || mode == 6) {
                    float h0 = v0 + __ldg(bias + col);
                    float h1 = v1 + __ldg(bias + col + 1);
                    if (mode == 4) { h0 = gelu_f(h0); h1 = gelu_f(h1); }
                    __half2 hp; hp.x = __float2half(h0); hp.y = __float2half(h1);
                    *(__half2*)(outh + (size_t)r * ldo + col) = hp;
                } else {
                    v0 += __ldg(bias + col);  v1 += __ldg(bias + col + 1);
                    if (mode == 3) {
                        float2 a = *(const float2*)(aux + (size_t)r * ldo + col);
                        *(float2*)(out + (size_t)r * ldo + col) = make_float2(v0 + a.x, v1 + a.y);
                    } else { // mode 2
                        float2 a = *(const float2*)(aux + g2 * 256 + col);
                        *(float2*)(out + g2 * 256 + col) = make_float2(v0 + a.x, v1 + a.y);
                    }
                }
            }
        }
    }
}

// ---------------- deformable sampling + fused softmax -> D fp16 -----------------
// Thread-per-token mapping: scalar coord/weight math once per token (not x32 lanes).
// sval padded to stride 33: corner-gather banks = (tok + ch) % 32, conflict-free.
#define SSTR 33
__global__ void __launch_bounds__(128, 8) k_sample()
{
    __shared__ float sval[NTOK * SSTR];
    int win  = blockIdx.x >> 3;
    int head = blockIdx.x & 7;
    int tid = threadIdx.x;

    // load value plane (fp16 -> fp32), 98 rows x 32 ch
    const __half* vplane = g_hh + (size_t)win * NTOK * CC + head * HDIM;
    for (int i = tid; i < NTOK * 4; i += 128) {
        int s0 = i >> 2, seg = i & 3;
        union { uint4 u; __half h[8]; } pk;
        pk.u = *(const uint4*)(vplane + (size_t)s0 * CC + seg * 8);
        #pragma unroll
        for (int k = 0; k < 8; k++) sval[s0 * SSTR + seg * 8 + k] = __half2float(pk.h[k]);
    }
    __syncthreads();

    int nn = tid;
    if (nn < NTOK) {
        int t = win * NTOK + nn;
        int z = nn / 49, rm = nn % 49, y = rm / 7, xq = rm % 7;
        const float4* offp = (const float4*)(g_offb + (size_t)t * 96 + head * 12);
        float4 o0 = offp[0], o1 = offp[1], o2 = offp[2];
        float offs[12] = { o0.x, o0.y, o0.z, o0.w, o1.x, o1.y, o1.z, o1.w,
                           o2.x, o2.y, o2.z, o2.w };
        float4 lg = *(const float4*)(g_awb + (size_t)t * 32 + head * 4);
        float mx = fmaxf(fmaxf(lg.x, lg.y), fmaxf(lg.z, lg.w));
        float e0 = __expf(lg.x - mx), e1 = __expf(lg.y - mx);
        float e2 = __expf(lg.z - mx), e3 = __expf(lg.w - mx);
        float inv = 1.f / (e0 + e1 + e2 + e3);
        float awv[4] = { e0 * inv, e1 * inv, e2 * inv, e3 * inv };

        float acc[32];
        #pragma unroll
        for (int c = 0; c < 32; c++) acc[c] = 0.f;

        #pragma unroll
        for (int p = 0; p < 4; p++) {
            float px = xq + offs[p * 3 + 0];
            float py = y  + offs[p * 3 + 1];
            float pz = z  + offs[p * 3 + 2];
            float fx0 = floorf(px), fy0 = floorf(py), fz0 = floorf(pz);
            float fx = px - fx0, fy = py - fy0, fz = pz - fz0;
            int ix = (int)fx0, iy = (int)fy0, iz = (int)fz0;
            float wx0 = (ix >= 0 && ix < 7)   ? 1.f - fx : 0.f;
            float wx1 = (ix >= -1 && ix < 6)  ? fx       : 0.f;
            float wy0 = (iy >= 0 && iy < 7)   ? 1.f - fy : 0.f;
            float wy1 = (iy >= -1 && iy < 6)  ? fy       : 0.f;
            float wz0 = (iz == 0 || iz == 1)  ? awv[p] * (1.f - fz) : 0.f;
            float wz1 = (iz == -1 || iz == 0) ? awv[p] * fz         : 0.f;
            int cx0 = min(max(ix, 0), 6),  cx1 = min(max(ix + 1, 0), 6);
            int cy0 = min(max(iy, 0), 6),  cy1 = min(max(iy + 1, 0), 6);
            int cz0 = min(max(iz, 0), 1),  cz1 = min(max(iz + 1, 0), 1);

            float w[8];
            int   b[8];
            w[0] = wz0 * wy0 * wx0;  b[0] = ((cz0 * 7 + cy0) * 7 + cx0) * SSTR;
            w[1] = wz0 * wy0 * wx1;  b[1] = ((cz0 * 7 + cy0) * 7 + cx1) * SSTR;
            w[2] = wz0 * wy1 * wx0;  b[2] = ((cz0 * 7 + cy1) * 7 + cx0) * SSTR;
            w[3] = wz0 * wy1 * wx1;  b[3] = ((cz0 * 7 + cy1) * 7 + cx1) * SSTR;
            w[4] = wz1 * wy0 * wx0;  b[4] = ((cz1 * 7 + cy0) * 7 + cx0) * SSTR;
            w[5] = wz1 * wy0 * wx1;  b[5] = ((cz1 * 7 + cy0) * 7 + cx1) * SSTR;
            w[6] = wz1 * wy1 * wx0;  b[6] = ((cz1 * 7 + cy1) * 7 + cx0) * SSTR;
            w[7] = wz1 * wy1 * wx1;  b[7] = ((cz1 * 7 + cy1) * 7 + cx1) * SSTR;

            #pragma unroll
            for (int corner = 0; corner < 8; corner++) {
                float wc = w[corner];
                const float* sp = sval + b[corner];
                #pragma unroll
                for (int c = 0; c < 32; c++) acc[c] += wc * sp[c];
            }
        }

        // store 32 fp16 channels (4 x uint4)
        __half* dst = g_act2h + (size_t)t * CC + head * HDIM;
        #pragma unroll
        for (int s0 = 0; s0 < 4; s0++) {
            union { uint4 u; __half h[8]; } pk;
            #pragma unroll
            for (int k = 0; k < 8; k++) pk.h[k] = __float2half(acc[s0 * 8 + k]);
            *(uint4*)(dst + s0 * 8) = pk.u;
        }
    }
}

// ---------------- residual(xw fp16 + attn fp16) + LN (anorm) -> acth ------------
__global__ void k_addln(const float* __restrict__ gg, const float* __restrict__ bb)
{
    int warp = threadIdx.x >> 5, lane = threadIdx.x & 31;
    int t = blockIdx.x * 8 + warp;
    size_t o = (size_t)t * CC + lane * 8;
    union { uint4 u; __half h[8]; } xa, ea;
    xa.u = *(const uint4*)(g_acth + o);
    ea.u = *(const uint4*)(g_hh + (size_t)TOT * CC + o);
    float vv[8];
    #pragma unroll
    for (int i = 0; i < 8; i++) vv[i] = __half2float(xa.h[i]) + __half2float(ea.h[i]);
    float s = 0.f;
    #pragma unroll
    for (int i = 0; i < 8; i++) s += vv[i];
    float mean = warp_sum(s) * (1.f / 256.f);
    float s2 = 0.f;
    #pragma unroll
    for (int i = 0; i < 8; i++) { vv[i] -= mean; s2 += vv[i] * vv[i]; }
    float rstd = rsqrtf(warp_sum(s2) * (1.f / 256.f) + 1e-5f);
    float4 ga = *((const float4*)(gg) + lane * 2), gb = *((const float4*)(gg) + lane * 2 + 1);
    float4 ba = *((const float4*)(bb) + lane * 2), b2 = *((const float4*)(bb) + lane * 2 + 1);
    float gv[8] = { ga.x, ga.y, ga.z, ga.w, gb.x, gb.y, gb.z, gb.w };
    float bv[8] = { ba.x, ba.y, ba.z, ba.w, b2.x, b2.y, b2.z, b2.w };
    union { uint4 u; __half hx[8]; } pk;
    #pragma unroll
    for (int i = 0; i < 8; i++) pk.hx[i] = __float2half(vv[i] * rstd * gv[i] + bv[i]);
    *(uint4*)(g_acth + o) = pk.u;
}

// ---------------- LN2, warp per token -> acth fp16 ------------------------------
__global__ void k_ln2(const float* __restrict__ xin,
                      const float* __restrict__ gg, const float* __restrict__ bb)
{
    int warp = threadIdx.x >> 5, lane = threadIdx.x & 31;
    int t = blockIdx.x * 8 + warp;
    size_t o = (size_t)t * CC + lane * 8;
    float4 a0 = *(const float4*)(xin + o), a1 = *(const float4*)(xin + o + 4);
    float vv[8] = { a0.x, a0.y, a0.z, a0.w, a1.x, a1.y, a1.z, a1.w };
    float s = 0.f;
    #pragma unroll
    for (int i = 0; i < 8; i++) s += vv[i];
    float mean = warp_sum(s) * (1.f / 256.f);
    float s2 = 0.f;
    #pragma unroll
    for (int i = 0; i < 8; i++) { vv[i] -= mean; s2 += vv[i] * vv[i]; }
    float rstd = rsqrtf(warp_sum(s2) * (1.f / 256.f) + 1e-5f);
    float4 ga = *((const float4*)(gg) + lane * 2), gb = *((const float4*)(gg) + lane * 2 + 1);
    float4 ba = *((const float4*)(bb) + lane * 2), b2 = *((const float4*)(bb) + lane * 2 + 1);
    float gv[8] = { ga.x, ga.y, ga.z, ga.w, gb.x, gb.y, gb.z, gb.w };
    float bv[8] = { ba.x, ba.y, ba.z, ba.w, b2.x, b2.y, b2.z, b2.w };
    union { uint4 u; __half hx[8]; } pk;
    #pragma unroll
    for (int i = 0; i < 8; i++) pk.hx[i] = __float2half(vv[i] * rstd * gv[i] + bv[i]);
    *(uint4*)(g_acth + o) = pk.u;
}

// ---------------- launch --------------------------------------------------------
extern "C" void kernel_launch(void* const* d_in, const int* in_sizes, int n_in,
                              void* d_out, int out_size)
{
    (void)in_sizes; (void)n_in; (void)out_size;
    const float* x     = (const float*)d_in[0];
    const float* mask  = (const float*)d_in[1];
    const float* n1g   = (const float*)d_in[2];
    const float* n1b   = (const float*)d_in[3];
    const float* valw  = (const float*)d_in[4];
    const float* valb  = (const float*)d_in[5];
    const float* offw  = (const float*)d_in[6];
    const float* offbi = (const float*)d_in[7];
    const float* aww   = (const float*)d_in[8];
    const float* awbi  = (const float*)d_in[9];
    const float* outw  = (const float*)d_in[10];
    const float* outbi = (const float*)d_in[11];
    const float* ang   = (const float*)d_in[12];
    const float* anb   = (const float*)d_in[13];
    const float* projw = (const float*)d_in[14];
    const float* projb = (const float*)d_in[15];
    const float* n2g   = (const float*)d_in[16];
    const float* n2b   = (const float*)d_in[17];
    const float* fc1w  = (const float*)d_in[18];
    const float* fc1b  = (const float*)d_in[19];
    const float* fc2w  = (const float*)d_in[20];
    const float* fc2b  = (const float*)d_in[21];
    float* out = (float*)d_out;

    float *pOff, *pAw;
    __half *pActh, *pAct2h, *pHh, *pWh;
    cudaGetSymbolAddress((void**)&pOff,  g_offb);
    cudaGetSymbolAddress((void**)&pAw,   g_awb);
    cudaGetSymbolAddress((void**)&pActh, g_acth);
    cudaGetSymbolAddress((void**)&pAct2h,g_act2h);
    cudaGetSymbolAddress((void**)&pHh,   g_hh);
    cudaGetSymbolAddress((void**)&pWh,   g_wh);
    __half* pAttn = pHh + (size_t)TOT * CC;   // attn-out plane inside g_hh

    const int SMEM = 98304;   // 3 stages x 32KB
    cudaFuncSetAttribute(k_hgemm, cudaFuncAttributeMaxDynamicSharedMemorySize, SMEM);

    const int MT = TOT / 128;    // 392 row tiles
    const int LNG = TOT / 8;     // warp per token

    // 0. all weight converts in one launch
    k_wconv_all<<<2944, 256>>>(valw, offw, aww, outw, projw, fc1w, fc2w);
    // 1. LN1 + partition + diag -> acth (xw fp16), act2h (q fp16)
    k_ln1diag<<<LNG, 256>>>(x, mask, n1g, n1b);
    // 2+3 fused. bx<2: value = xw @ val_w -> g_hh value plane (fp16);
    //            bx==2: off/aw = q @ [off_w|aw_w] -> offb/awb (fp32)
    k_hgemm<<<dim3(3, MT), 256, SMEM>>>(pActh, pWh, pAct2h, pWh + 65536,
                                        valb, offbi, awbi,
                                        pOff, pAw, nullptr, pHh, 256, 256, 7);
    // 4. deformable sampling (softmax fused) -> act2h (D fp16)
    k_sample<<<NWIN * NHD, 128>>>();
    // 5. attn out = D @ out_w + b -> attn plane (fp16)
    k_hgemm<<<dim3(2, MT), 256, SMEM>>>(pAct2h, pWh + 98304, nullptr, nullptr,
                                        outbi, nullptr, nullptr,
                                        nullptr, nullptr, nullptr, pAttn, 256, 256, 6);
    // 6. acth = LN(xw + attn) with anorm
    k_addln<<<LNG, 256>>>(ang, anb);
    // 7. window-reverse + residual: out = x + (acth @ proj_w + b)
    k_hgemm<<<dim3(2, MT), 256, SMEM>>>(pActh, pWh + 163840, nullptr, nullptr,
                                        projb, nullptr, nullptr,
                                        out, nullptr, x, nullptr, 256, 256, 2);
    // 8. acth = LN2(out)
    k_ln2<<<LNG, 256>>>(out, n2g, n2b);
    // 9. H = gelu(acth @ fc1_w + b) -> g_hh (fp16 hidden)
    k_hgemm<<<dim3(8, MT), 256, SMEM>>>(pActh, pWh + 229376, nullptr, nullptr,
                                        fc1b, nullptr, nullptr,
                                        nullptr, nullptr, nullptr, pHh, 256, 1024, 4);
    // 10. out += H @ fc2_w + b
    k_hgemm<<<dim3(2, MT), 256, SMEM>>>(pHh, pWh + 491520, nullptr, nullptr,
                                        fc2b, nullptr, nullptr,
                                        out, nullptr, out, nullptr, 1024, 256, 3);
}